// round 2
// baseline (speedup 1.0000x reference)
#include <cuda_runtime.h>

// Shapes (fixed by the problem): B=8, F=256, K=64, ED=256, TP=4, W=16, H=4
// f = 64, nW = 4, L = 64, N = 2048 windows, 256 distinct (fi,wi) windows for A.

#define XSTR 260   // xs/ys row stride (floats): 4-aligned for float4, bank-shifts rows
#define WSTR 258   // transposed-Wp chunk row stride: even (8B align), 2*kk bank shift
#define ASTR 66    // A tile row stride
#define L_TOK 64
#define ED 256

__device__ float g_A[256 * 64 * 64];   // per-window A = deg @ eb  (4 MB scratch)

__device__ __forceinline__ unsigned long long pack2(float lo, float hi) {
    unsigned long long r;
    asm("mov.b64 %0, {%1, %2};" : "=l"(r) : "f"(lo), "f"(hi));
    return r;
}
__device__ __forceinline__ void ffma2(unsigned long long& d,
                                      unsigned long long a,
                                      unsigned long long b) {
    asm("fma.rn.f32x2 %0, %1, %2, %0;" : "+l"(d) : "l"(a), "l"(b));
}

// ---------------------------------------------------------------------------
// Kernel 1: A[w] = deg[w] @ eb[w],  w in [0,256), each 64x64x64.
// ---------------------------------------------------------------------------
__global__ __launch_bounds__(256) void pab_a_kernel(const float* __restrict__ deg,
                                                    const float* __restrict__ eb) {
    __shared__ float ds[64 * 65];
    __shared__ float es[64 * 65];
    const int w = blockIdx.x, tid = threadIdx.x;
    const float* D = deg + w * 4096;
    const float* E = eb + w * 4096;
    for (int i = tid; i < 4096; i += 256) {
        ds[(i >> 6) * 65 + (i & 63)] = D[i];
        es[(i >> 6) * 65 + (i & 63)] = E[i];
    }
    __syncthreads();
    const int p = tid >> 2;            // output row 0..63
    const int q0 = (tid & 3) * 16;     // 16 output cols
    float acc[16];
#pragma unroll
    for (int j = 0; j < 16; ++j) acc[j] = 0.f;
    for (int r = 0; r < 64; ++r) {
        float d = ds[p * 65 + r];
#pragma unroll
        for (int j = 0; j < 16; ++j) acc[j] = fmaf(d, es[r * 65 + q0 + j], acc[j]);
    }
    float* Aw = g_A + w * 4096 + p * 64 + q0;
#pragma unroll
    for (int j = 0; j < 16; ++j) Aw[j] = acc[j];
}

// ---------------------------------------------------------------------------
// Kernel 2: fused window-partition + LayerNorm + (xn @ Wp^T + bp) + (A @ y)
//           + window-reverse.  One CTA per window (grid 2048, 256 threads).
// Thread tiling for both GEMMs: ty = warp (8 rows each), tx = lane
// (4 column-pairs: e = 2*tx + 64*j).  All FMAs are packed f32x2.
// ---------------------------------------------------------------------------
__global__ __launch_bounds__(256, 1)
void pab_main_kernel(const float* __restrict__ x,
                     const float* __restrict__ gamma,
                     const float* __restrict__ beta,
                     const float* __restrict__ Wp,
                     const float* __restrict__ bp,
                     float* __restrict__ out) {
    extern __shared__ float sm[];
    float* xs = sm;                    // [64][XSTR] normalized input tile
    float* ys = sm + 64 * XSTR;        // [64][XSTR] projected tile (also gamma/beta scratch)
    float* wk = ys + 64 * XSTR;        // [32][WSTR] Wp chunk (transposed) / later A [64][ASTR]

    const int tid = threadIdx.x;
    const int n = blockIdx.x;
    const int rem = n & 255;           // fi*4 + wi  == window id for A
    const int b = n >> 8;
    const int fi = rem >> 2;
    const int wi = rem & 3;
    // global float offset of (row l=0, e=0) of this window
    const int base = ((b * 256 + fi * 4) * 64 + wi * 16) * ED;

    // stash gamma/beta in ys rows 0/1 (free until GEMM1 output)
    ys[tid] = gamma[tid];
    ys[XSTR + tid] = beta[tid];

    // ---- load window tile (float4, coalesced) ----
    for (int i = tid; i < 64 * 64; i += 256) {
        int l = i >> 6;
        int e4 = (i & 63) << 2;
        int g = base + (((l >> 4) * 64) + (l & 15)) * ED + e4;   // tp*64 + ws rows
        float4 v = *reinterpret_cast<const float4*>(x + g);
        *reinterpret_cast<float4*>(xs + l * XSTR + e4) = v;
    }
    __syncthreads();

    // ---- LayerNorm: one warp per row, 8 rows per warp ----
    const int warp = tid >> 5, lane = tid & 31;
#pragma unroll
    for (int r = 0; r < 8; ++r) {
        const int l = warp * 8 + r;
        float v[8], s = 0.f, s2 = 0.f;
#pragma unroll
        for (int u = 0; u < 8; ++u) {
            float t = xs[l * XSTR + lane + 32 * u];
            v[u] = t; s += t; s2 = fmaf(t, t, s2);
        }
#pragma unroll
        for (int o = 16; o > 0; o >>= 1) {
            s += __shfl_xor_sync(0xffffffffu, s, o);
            s2 += __shfl_xor_sync(0xffffffffu, s2, o);
        }
        const float mu = s * (1.f / 256.f);
        const float var = fmaf(-mu, mu, s2 * (1.f / 256.f));
        const float rstd = rsqrtf(var + 1e-5f);
#pragma unroll
        for (int u = 0; u < 8; ++u) {
            int e = lane + 32 * u;
            xs[l * XSTR + e] = (v[u] - mu) * rstd * ys[e] + ys[XSTR + e];
        }
    }

    // ---- GEMM1: y[l][e] = sum_k xn[l][k] * Wp[e][k] + bp[e] ----
    const int ty = warp, tx = lane;
    unsigned long long acc[8][4];
#pragma unroll
    for (int j = 0; j < 4; ++j) {
        const int e = tx * 2 + 64 * j;
        const unsigned long long init = pack2(bp[e], bp[e + 1]);
#pragma unroll
        for (int i = 0; i < 8; ++i) acc[i][j] = init;
    }

    for (int c = 0; c < 8; ++c) {
        const int k0 = c * 32;
        __syncthreads();                       // consumers of previous chunk done
        {
            // transpose-load Wp[e][k0..k0+31] -> wk[kk][e]
            const int kk = tid & 31, e0 = tid >> 5;
#pragma unroll
            for (int r = 0; r < 32; ++r) {
                const int e = e0 + 8 * r;
                wk[kk * WSTR + e] = Wp[e * ED + k0 + kk];   // LDG coalesced, STS ~conflict-free
            }
        }
        __syncthreads();
#pragma unroll 4
        for (int kk = 0; kk < 32; ++kk) {
            unsigned long long a2[8], b2[4];
#pragma unroll
            for (int i = 0; i < 8; ++i) {      // broadcast LDS (all lanes same addr)
                const float a = xs[(ty * 8 + i) * XSTR + k0 + kk];
                a2[i] = pack2(a, a);
            }
#pragma unroll
            for (int j = 0; j < 4; ++j)        // LDS.64, <=2-way conflict
                b2[j] = *reinterpret_cast<const unsigned long long*>(
                    wk + kk * WSTR + tx * 2 + 64 * j);
#pragma unroll
            for (int i = 0; i < 8; ++i)
#pragma unroll
                for (int j = 0; j < 4; ++j) ffma2(acc[i][j], a2[i], b2[j]);
        }
    }

    // write y tile to smem (STS.64)
#pragma unroll
    for (int i = 0; i < 8; ++i)
#pragma unroll
        for (int j = 0; j < 4; ++j)
            *reinterpret_cast<unsigned long long*>(
                ys + (ty * 8 + i) * XSTR + tx * 2 + 64 * j) = acc[i][j];
    __syncthreads();                            // all GEMM1 wk reads + ys writes done

    // ---- load A[rem] into wk region ----
    {
        const float* Aw = g_A + rem * 4096;
        for (int i = tid; i < 4096; i += 256)
            wk[(i >> 6) * ASTR + (i & 63)] = Aw[i];
    }
    __syncthreads();

    // ---- GEMM2: z[p][e] = sum_q A[p][q] * y[q][e] ----
    unsigned long long z[8][4];
#pragma unroll
    for (int i = 0; i < 8; ++i)
#pragma unroll
        for (int j = 0; j < 4; ++j) z[i][j] = 0ull;

#pragma unroll 4
    for (int q = 0; q < 64; ++q) {
        unsigned long long a2[8], b2[4];
#pragma unroll
        for (int i = 0; i < 8; ++i) {           // broadcast LDS
            const float a = wk[(ty * 8 + i) * ASTR + q];
            a2[i] = pack2(a, a);
        }
#pragma unroll
        for (int j = 0; j < 4; ++j)
            b2[j] = *reinterpret_cast<const unsigned long long*>(
                ys + q * XSTR + tx * 2 + 64 * j);
#pragma unroll
        for (int i = 0; i < 8; ++i)
#pragma unroll
            for (int j = 0; j < 4; ++j) ffma2(z[i][j], a2[i], b2[j]);
    }

    // ---- window-reverse store (STG.64, coalesced across lanes) ----
#pragma unroll
    for (int i = 0; i < 8; ++i) {
        const int l = ty * 8 + i;
        const int g = base + (((l >> 4) * 64) + (l & 15)) * ED;
#pragma unroll
        for (int j = 0; j < 4; ++j)
            *reinterpret_cast<unsigned long long*>(out + g + tx * 2 + 64 * j) = z[i][j];
    }
}

// ---------------------------------------------------------------------------
extern "C" void kernel_launch(void* const* d_in, const int* in_sizes, int n_in,
                              void* d_out, int out_size) {
    const float* x     = (const float*)d_in[0];
    const float* gamma = (const float*)d_in[1];
    const float* beta  = (const float*)d_in[2];
    const float* Wp    = (const float*)d_in[3];
    const float* bp    = (const float*)d_in[4];
    const float* eb    = (const float*)d_in[5];
    const float* deg   = (const float*)d_in[6];
    float* out = (float*)d_out;

    const size_t SMEM = (size_t)(2 * 64 * XSTR + 32 * WSTR) * sizeof(float); // ~162 KB
    cudaFuncSetAttribute(pab_main_kernel,
                         cudaFuncAttributeMaxDynamicSharedMemorySize, (int)SMEM);

    pab_a_kernel<<<256, 256>>>(deg, eb);
    pab_main_kernel<<<2048, 256, SMEM>>>(x, gamma, beta, Wp, bp, out);
}

// round 4
// speedup vs baseline: 2.1828x; 2.1828x over previous
#include <cuda_runtime.h>
#include <cuda_bf16.h>

#define ED 256

// ---- smem layout (bytes). xs rows: 256 cols + 8 pad = 264 bf16 = 528B ----
#define XROW 528u
#define OFF_XH 0u              // u/xn hi: 128 x 264 bf16 = 67584
#define OFF_XL 67584u          // lo
#define OFF_A  135168u         // A_w hi (9216) + lo (9216); 64 x (64+8) bf16 rows
#define OFF_WT 153600u         // Wt tile: hi 9216 + lo 9216 (64 x 72 bf16)
#define OFF_BP 172032u         // 256 f32
#define OFF_RS 173056u         // 64 f32
#define SMEM_BYTES 173312u

// ---- global scratch ----
__device__ __align__(16) unsigned short g_Ah[256 * 4096];
__device__ __align__(16) unsigned short g_Al[256 * 4096];
__device__ __align__(16) unsigned short g_Wth[65536];  // blocked (kt*4+nc) 64x64 tiles
__device__ __align__(16) unsigned short g_Wtl[65536];
__device__ float g_rsA[256 * 64];

// ---------------------------------------------------------------------------
__device__ __forceinline__ unsigned smem_u32(const void* p) {
    unsigned a;
    asm("{ .reg .u64 t; cvta.to.shared.u64 t, %1; cvt.u32.u64 %0, t; }" : "=r"(a) : "l"(p));
    return a;
}
__device__ __forceinline__ void ldsm4(unsigned r[4], unsigned a) {
    asm volatile("ldmatrix.sync.aligned.m8n8.x4.shared.b16 {%0,%1,%2,%3}, [%4];"
                 : "=r"(r[0]), "=r"(r[1]), "=r"(r[2]), "=r"(r[3]) : "r"(a));
}
__device__ __forceinline__ void ldsm4t(unsigned r[4], unsigned a) {
    asm volatile("ldmatrix.sync.aligned.m8n8.x4.trans.shared.b16 {%0,%1,%2,%3}, [%4];"
                 : "=r"(r[0]), "=r"(r[1]), "=r"(r[2]), "=r"(r[3]) : "r"(a));
}
__device__ __forceinline__ void mma16816(float d[4], const unsigned a[4], const unsigned b[2]) {
    asm volatile("mma.sync.aligned.m16n8k16.row.col.f32.bf16.bf16.f32 "
                 "{%0,%1,%2,%3}, {%4,%5,%6,%7}, {%8,%9}, {%0,%1,%2,%3};"
                 : "+f"(d[0]), "+f"(d[1]), "+f"(d[2]), "+f"(d[3])
                 : "r"(a[0]), "r"(a[1]), "r"(a[2]), "r"(a[3]), "r"(b[0]), "r"(b[1]));
}
__device__ __forceinline__ void split_bf16(float v, unsigned short& h, unsigned short& l) {
    __nv_bfloat16 bh = __float2bfloat16_rn(v);
    __nv_bfloat16 bl = __float2bfloat16_rn(v - __bfloat162float(bh));
    h = __bfloat16_as_ushort(bh);
    l = __bfloat16_as_ushort(bl);
}

// ---------------------------------------------------------------------------
// Kernel 1: A[w] = deg[w] @ eb[w] (fp32), store bf16 hi/lo row-major + rowsums.
// ---------------------------------------------------------------------------
__global__ __launch_bounds__(256) void pab_a_kernel(const float* __restrict__ deg,
                                                    const float* __restrict__ eb) {
    __shared__ float ds[64 * 65];
    __shared__ float es[64 * 65];
    const int w = blockIdx.x, tid = threadIdx.x;
    const float* D = deg + w * 4096;
    const float* E = eb + w * 4096;
    for (int i = tid; i < 4096; i += 256) {
        ds[(i >> 6) * 65 + (i & 63)] = D[i];
        es[(i >> 6) * 65 + (i & 63)] = E[i];
    }
    __syncthreads();
    const int p = tid >> 2;
    const int q0 = (tid & 3) * 16;
    float acc[16];
#pragma unroll
    for (int j = 0; j < 16; ++j) acc[j] = 0.f;
    for (int r = 0; r < 64; ++r) {
        float d = ds[p * 65 + r];
#pragma unroll
        for (int j = 0; j < 16; ++j) acc[j] = fmaf(d, es[r * 65 + q0 + j], acc[j]);
    }
    float s = 0.f;
#pragma unroll
    for (int j = 0; j < 16; ++j) s += acc[j];
    s += __shfl_xor_sync(0xffffffffu, s, 1);
    s += __shfl_xor_sync(0xffffffffu, s, 2);
    if ((tid & 3) == 0) g_rsA[w * 64 + p] = s;
#pragma unroll
    for (int j = 0; j < 16; ++j) {
        unsigned short h, l;
        split_bf16(acc[j], h, l);
        g_Ah[w * 4096 + p * 64 + q0 + j] = h;
        g_Al[w * 4096 + p * 64 + q0 + j] = l;
    }
}

// ---------------------------------------------------------------------------
// Kernel 2: Wt[k][n] = Wp[n][k], bf16 hi/lo, blocked into 16 tiles of 64x64:
// tile index (kt*4+nc), element kk*64+nn.
// ---------------------------------------------------------------------------
__global__ __launch_bounds__(256) void pab_w_kernel(const float* __restrict__ Wp) {
    const int idx = blockIdx.x * 256 + threadIdx.x;
    const int k = idx & 255, n = idx >> 8;
    unsigned short h, l;
    split_bf16(Wp[n * 256 + k], h, l);
    const int o = ((k >> 6) * 4 + (n >> 6)) * 4096 + (k & 63) * 64 + (n & 63);
    g_Wth[o] = h;
    g_Wtl[o] = l;
}

// ---------------------------------------------------------------------------
// Kernel 3: fused LN + u = A@xn (in-place) + out = u@Wt + rs*bp.
// One CTA = 2 windows (128 tokens), 8 warps.
// ---------------------------------------------------------------------------
__global__ __launch_bounds__(256, 1)
void pab_main_kernel(const float* __restrict__ x,
                     const float* __restrict__ gamma,
                     const float* __restrict__ beta,
                     const float* __restrict__ bp,
                     float* __restrict__ out) {
    extern __shared__ __align__(16) char smb[];
    const unsigned smu = smem_u32(smb);

    const int tid = threadIdx.x;
    const int lane = tid & 31, wid = tid >> 5;
    const int rem = blockIdx.x & 255;         // fi*4 + wi
    const int pair = blockIdx.x >> 8;         // 0..3
    const int fi = rem >> 2, wi = rem & 3;
    int wb[2];
#pragma unroll
    for (int w = 0; w < 2; ++w)
        wb[w] = (((pair * 2 + w) * 256 + fi * 4) * 64 + wi * 16) * ED;

    // ---- setup: bp, rsA, A_w (hi/lo) into smem ----
    ((float*)(smb + OFF_BP))[tid] = bp[tid];
    if (tid < 64) ((float*)(smb + OFF_RS))[tid] = g_rsA[rem * 64 + tid];
    {
        // 1024 uint4: hl = j>>9, row = (j&511)>>3, c8 = j&7
        for (int j = tid; j < 1024; j += 256) {
            const int hl = j >> 9, jj = j & 511;
            const uint4 v = ((const uint4*)(hl ? g_Al : g_Ah))[rem * 512 + jj];
            *(uint4*)(smb + OFF_A + hl * 9216 + (jj >> 3) * 144 + (jj & 7) * 16) = v;
        }
    }

    // ---- LayerNorm -> xn hi/lo (padded row-major) ----
    {
        float gr[8], br[8];
#pragma unroll
        for (int u = 0; u < 8; ++u) { gr[u] = gamma[lane * 8 + u]; br[u] = beta[lane * 8 + u]; }
        for (int r = 0; r < 16; ++r) {
            const int m = wid * 16 + r;
            const int win = m >> 6, l = m & 63;
            const float* xr = x + wb[win] + ((l >> 4) * 64 + (l & 15)) * ED;
            float4 a4 = *(const float4*)(xr + lane * 8);
            float4 b4 = *(const float4*)(xr + lane * 8 + 4);
            float v[8] = {a4.x, a4.y, a4.z, a4.w, b4.x, b4.y, b4.z, b4.w};
            float s = 0.f, s2 = 0.f;
#pragma unroll
            for (int u = 0; u < 8; ++u) { s += v[u]; s2 = fmaf(v[u], v[u], s2); }
#pragma unroll
            for (int o = 16; o > 0; o >>= 1) {
                s += __shfl_xor_sync(0xffffffffu, s, o);
                s2 += __shfl_xor_sync(0xffffffffu, s2, o);
            }
            const float mu = s * (1.f / 256.f);
            const float var = fmaf(-mu, mu, s2 * (1.f / 256.f));
            const float rstd = rsqrtf(var + 1e-5f);
            unsigned hh[8], ll[8];
#pragma unroll
            for (int u = 0; u < 8; ++u) {
                const float xn = (v[u] - mu) * rstd * gr[u] + br[u];
                unsigned short h, l2;
                split_bf16(xn, h, l2);
                hh[u] = h; ll[u] = l2;
            }
            uint4 ph, pl;
            ph.x = hh[0] | (hh[1] << 16); ph.y = hh[2] | (hh[3] << 16);
            ph.z = hh[4] | (hh[5] << 16); ph.w = hh[6] | (hh[7] << 16);
            pl.x = ll[0] | (ll[1] << 16); pl.y = ll[2] | (ll[3] << 16);
            pl.z = ll[4] | (ll[5] << 16); pl.w = ll[6] | (ll[7] << 16);
            *(uint4*)(smb + OFF_XH + m * XROW + lane * 16) = ph;
            *(uint4*)(smb + OFF_XL + m * XROW + lane * 16) = pl;
        }
    }
    __syncthreads();

    // ---- Phase B: u[p][e] = sum_q A[p][q] * xn[q][e], in-place per 64-col chunk ----
    const int w = wid >> 2, mb = wid & 3;
    const int lr = lane & 15, lc = lane >> 4;
    for (int nc = 0; nc < 4; ++nc) {
        float acc[8][4];
#pragma unroll
        for (int f = 0; f < 8; ++f)
#pragma unroll
            for (int j = 0; j < 4; ++j) acc[f][j] = 0.f;

#pragma unroll
        for (int ks = 0; ks < 4; ++ks) {
            unsigned Ah[4], Al[4];
            const unsigned aoff = (unsigned)((mb * 16 + lr) * 144 + (ks * 16 + lc * 8) * 2);
            ldsm4(Ah, smu + OFF_A + aoff);
            ldsm4(Al, smu + OFF_A + 9216u + aoff);
            const unsigned brow = (unsigned)((w * 64 + ks * 16 + lr) * XROW);
#pragma unroll
            for (int f4 = 0; f4 < 4; ++f4) {
                const unsigned bcol = (unsigned)((nc * 64 + f4 * 16 + lc * 8) * 2);
                unsigned Bh[4], Bl[4];
                ldsm4t(Bh, smu + OFF_XH + brow + bcol);
                ldsm4t(Bl, smu + OFF_XL + brow + bcol);
                mma16816(acc[2 * f4],     Ah, Bh);
                mma16816(acc[2 * f4],     Al, Bh);
                mma16816(acc[2 * f4],     Ah, Bl);
                mma16816(acc[2 * f4 + 1], Ah, Bh + 2);
                mma16816(acc[2 * f4 + 1], Al, Bh + 2);
                mma16816(acc[2 * f4 + 1], Ah, Bl + 2);
            }
        }
        __syncthreads();   // all reads of chunk nc done -> safe to overwrite
        const int r0 = w * 64 + mb * 16 + (lane >> 2);
#pragma unroll
        for (int f = 0; f < 8; ++f) {
            const int c = nc * 64 + f * 8 + (lane & 3) * 2;
            unsigned short h0, l0, h1, l1;
            split_bf16(acc[f][0], h0, l0); split_bf16(acc[f][1], h1, l1);
            *(unsigned*)(smb + OFF_XH + r0 * XROW + c * 2) = (unsigned)h0 | ((unsigned)h1 << 16);
            *(unsigned*)(smb + OFF_XL + r0 * XROW + c * 2) = (unsigned)l0 | ((unsigned)l1 << 16);
            split_bf16(acc[f][2], h0, l0); split_bf16(acc[f][3], h1, l1);
            *(unsigned*)(smb + OFF_XH + (r0 + 8) * XROW + c * 2) = (unsigned)h0 | ((unsigned)h1 << 16);
            *(unsigned*)(smb + OFF_XL + (r0 + 8) * XROW + c * 2) = (unsigned)l0 | ((unsigned)l1 << 16);
        }
    }

    // ---- Phase C: out[m][n] = sum_k u[m][k] * Wt[k][n] + rs[m]*bp[n] ----
    const float* bps = (const float*)(smb + OFF_BP);
    const float* rss = (const float*)(smb + OFF_RS);
    float acc[8][4];
    uint4 th[2], tl[2];
    {   // prefetch tile 0 (nc=0, kt=0)
        const uint4* gh = (const uint4*)(g_Wth);
        const uint4* gl = (const uint4*)(g_Wtl);
        th[0] = gh[tid]; th[1] = gh[tid + 256];
        tl[0] = gl[tid]; tl[1] = gl[tid + 256];
    }
    for (int i = 0; i < 16; ++i) {
        const int kt = i & 3, nc = i >> 2;
        __syncthreads();      // previous tile consumed (or phase B writes done)
        {
            const int j0 = tid, j1 = tid + 256;
            *(uint4*)(smb + OFF_WT + (j0 >> 3) * 144 + (j0 & 7) * 16) = th[0];
            *(uint4*)(smb + OFF_WT + (j1 >> 3) * 144 + (j1 & 7) * 16) = th[1];
            *(uint4*)(smb + OFF_WT + 9216u + (j0 >> 3) * 144 + (j0 & 7) * 16) = tl[0];
            *(uint4*)(smb + OFF_WT + 9216u + (j1 >> 3) * 144 + (j1 & 7) * 16) = tl[1];
        }
        if (i < 15) {
            const int ii = i + 1;
            const int base = (((ii & 3) * 4 + (ii >> 2)) * 4096) >> 3;   // uint4 index
            const uint4* gh = (const uint4*)(g_Wth);
            const uint4* gl = (const uint4*)(g_Wtl);
            th[0] = gh[base + tid]; th[1] = gh[base + tid + 256];
            tl[0] = gl[base + tid]; tl[1] = gl[base + tid + 256];
        }
        __syncthreads();      // tile in smem
        if (kt == 0) {
#pragma unroll
            for (int f = 0; f < 8; ++f)
#pragma unroll
                for (int j = 0; j < 4; ++j) acc[f][j] = 0.f;
        }
#pragma unroll
        for (int ks = 0; ks < 4; ++ks) {
            unsigned Ah[4], Al[4];
            const unsigned aoff = (unsigned)((wid * 16 + lr) * XROW + (kt * 64 + ks * 16 + lc * 8) * 2);
            ldsm4(Ah, smu + OFF_XH + aoff);
            ldsm4(Al, smu + OFF_XL + aoff);
            const unsigned wrow = (unsigned)((ks * 16 + lr) * 144);
#pragma unroll
            for (int f4 = 0; f4 < 4; ++f4) {
                const unsigned wcol = (unsigned)((f4 * 16 + lc * 8) * 2);
                unsigned Bh[4], Bl[4];
                ldsm4t(Bh, smu + OFF_WT + wrow + wcol);
                ldsm4t(Bl, smu + OFF_WT + 9216u + wrow + wcol);
                mma16816(acc[2 * f4],     Ah, Bh);
                mma16816(acc[2 * f4],     Al, Bh);
                mma16816(acc[2 * f4],     Ah, Bl);
                mma16816(acc[2 * f4 + 1], Ah, Bh + 2);
                mma16816(acc[2 * f4 + 1], Al, Bh + 2);
                mma16816(acc[2 * f4 + 1], Ah, Bl + 2);
            }
        }
        if (kt == 3) {   // epilogue for this n-chunk: direct global store
            const int m0 = wid * 16 + (lane >> 2);
#pragma unroll
            for (int f = 0; f < 8; ++f) {
                const int c = nc * 64 + f * 8 + (lane & 3) * 2;
                const float b0 = bps[c], b1 = bps[c + 1];
#pragma unroll
                for (int half = 0; half < 2; ++half) {
                    const int m = m0 + half * 8;
                    const int win = m >> 6, l = m & 63;
                    const float rs = rss[l];
                    float2 v;
                    v.x = acc[f][half * 2 + 0] + rs * b0;
                    v.y = acc[f][half * 2 + 1] + rs * b1;
                    *(float2*)(out + wb[win] + ((l >> 4) * 64 + (l & 15)) * ED + c) = v;
                }
            }
        }
    }
}

// ---------------------------------------------------------------------------
extern "C" void kernel_launch(void* const* d_in, const int* in_sizes, int n_in,
                              void* d_out, int out_size) {
    const float* x     = (const float*)d_in[0];
    const float* gamma = (const float*)d_in[1];
    const float* beta  = (const float*)d_in[2];
    const float* Wp    = (const float*)d_in[3];
    const float* bp    = (const float*)d_in[4];
    const float* eb    = (const float*)d_in[5];
    const float* deg   = (const float*)d_in[6];
    float* out = (float*)d_out;

    cudaFuncSetAttribute(pab_main_kernel,
                         cudaFuncAttributeMaxDynamicSharedMemorySize, (int)SMEM_BYTES);

    pab_a_kernel<<<256, 256>>>(deg, eb);
    pab_w_kernel<<<256, 256>>>(Wp);
    pab_main_kernel<<<1024, 256, SMEM_BYTES>>>(x, gamma, beta, bp, out);
}

// round 5
// speedup vs baseline: 2.4935x; 1.1423x over previous
#include <cuda_runtime.h>
#include <cuda_fp16.h>

#define ED 256

// ---- smem layout (bytes). x rows: 256 cols + 8 pad = 264 fp16 = 528B ----
#define XROW 528u
#define OFF_XH 0u              // u/xn hi: 128 x 264 fp16 = 67584
#define OFF_XL 67584u          // lo
#define OFF_A  135168u         // A_w hi (9216) + lo (9216); 64 x 72 fp16 rows
#define OFF_WT 153600u         // Wt tile hi only: 64 x 72 fp16 = 9216
#define OFF_BP 162816u         // 256 f32
#define OFF_RS 163840u         // 64 f32
#define SMEM_BYTES 164096u

// ---- global scratch ----
__device__ __align__(16) unsigned short g_Ah[256 * 4096];
__device__ __align__(16) unsigned short g_Al[256 * 4096];
__device__ __align__(16) unsigned short g_Wth[65536];  // blocked (kt*4+nc) 64x64 fp16
__device__ float g_rsA[256 * 64];

// ---------------------------------------------------------------------------
__device__ __forceinline__ unsigned smem_u32(const void* p) {
    unsigned a;
    asm("{ .reg .u64 t; cvta.to.shared.u64 t, %1; cvt.u32.u64 %0, t; }" : "=r"(a) : "l"(p));
    return a;
}
__device__ __forceinline__ void ldsm4(unsigned r[4], unsigned a) {
    asm volatile("ldmatrix.sync.aligned.m8n8.x4.shared.b16 {%0,%1,%2,%3}, [%4];"
                 : "=r"(r[0]), "=r"(r[1]), "=r"(r[2]), "=r"(r[3]) : "r"(a));
}
__device__ __forceinline__ void ldsm4t(unsigned r[4], unsigned a) {
    asm volatile("ldmatrix.sync.aligned.m8n8.x4.trans.shared.b16 {%0,%1,%2,%3}, [%4];"
                 : "=r"(r[0]), "=r"(r[1]), "=r"(r[2]), "=r"(r[3]) : "r"(a));
}
__device__ __forceinline__ void mma16816(float d[4], const unsigned a[4], const unsigned b[2]) {
    asm volatile("mma.sync.aligned.m16n8k16.row.col.f32.f16.f16.f32 "
                 "{%0,%1,%2,%3}, {%4,%5,%6,%7}, {%8,%9}, {%0,%1,%2,%3};"
                 : "+f"(d[0]), "+f"(d[1]), "+f"(d[2]), "+f"(d[3])
                 : "r"(a[0]), "r"(a[1]), "r"(a[2]), "r"(a[3]), "r"(b[0]), "r"(b[1]));
}
__device__ __forceinline__ void split_f16(float v, unsigned short& h, unsigned short& l) {
    __half hh = __float2half_rn(v);
    __half ll = __float2half_rn(v - __half2float(hh));
    h = __half_as_ushort(hh);
    l = __half_as_ushort(ll);
}

// ---------------------------------------------------------------------------
// Kernel 1: A[w] = deg[w] @ eb[w] (fp32) -> fp16 hi/lo row-major + rowsums.
// grid 512: one CTA = half a window (32 output rows).
// ---------------------------------------------------------------------------
__global__ __launch_bounds__(256) void pab_a_kernel(const float* __restrict__ deg,
                                                    const float* __restrict__ eb) {
    __shared__ float ds[32 * 68];
    __shared__ float es[64 * 68];
    const int w = blockIdx.x >> 1, half = blockIdx.x & 1;
    const int tid = threadIdx.x;
    const float* D = deg + w * 4096 + half * 32 * 64;
    const float* E = eb + w * 4096;
    for (int i = tid; i < 4096; i += 256) es[(i >> 6) * 68 + (i & 63)] = E[i];
    for (int i = tid; i < 2048; i += 256) ds[(i >> 6) * 68 + (i & 63)] = D[i];
    __syncthreads();
    const int p = tid >> 3;            // local row 0..31
    const int q0 = (tid & 7) * 8;      // 8 output cols
    float acc[8];
#pragma unroll
    for (int j = 0; j < 8; ++j) acc[j] = 0.f;
#pragma unroll 4
    for (int r = 0; r < 64; ++r) {
        const float d = ds[p * 68 + r];
        const float4 e0 = *(const float4*)&es[r * 68 + q0];
        const float4 e1 = *(const float4*)&es[r * 68 + q0 + 4];
        acc[0] = fmaf(d, e0.x, acc[0]); acc[1] = fmaf(d, e0.y, acc[1]);
        acc[2] = fmaf(d, e0.z, acc[2]); acc[3] = fmaf(d, e0.w, acc[3]);
        acc[4] = fmaf(d, e1.x, acc[4]); acc[5] = fmaf(d, e1.y, acc[5]);
        acc[6] = fmaf(d, e1.z, acc[6]); acc[7] = fmaf(d, e1.w, acc[7]);
    }
    float s = 0.f;
#pragma unroll
    for (int j = 0; j < 8; ++j) s += acc[j];
    s += __shfl_xor_sync(0xffffffffu, s, 1);
    s += __shfl_xor_sync(0xffffffffu, s, 2);
    s += __shfl_xor_sync(0xffffffffu, s, 4);
    const int gp = half * 32 + p;
    if ((tid & 7) == 0) g_rsA[w * 64 + gp] = s;
    unsigned ph[4], pl[4];
#pragma unroll
    for (int j = 0; j < 4; ++j) {
        unsigned short h0, l0, h1, l1;
        split_f16(acc[2 * j], h0, l0);
        split_f16(acc[2 * j + 1], h1, l1);
        ph[j] = (unsigned)h0 | ((unsigned)h1 << 16);
        pl[j] = (unsigned)l0 | ((unsigned)l1 << 16);
    }
    *(uint4*)(g_Ah + w * 4096 + gp * 64 + q0) = make_uint4(ph[0], ph[1], ph[2], ph[3]);
    *(uint4*)(g_Al + w * 4096 + gp * 64 + q0) = make_uint4(pl[0], pl[1], pl[2], pl[3]);
}

// ---------------------------------------------------------------------------
// Kernel 2: Wt[k][n] = fp16(Wp[n][k]), blocked into 16 tiles of 64x64 (kt*4+nc).
// ---------------------------------------------------------------------------
__global__ __launch_bounds__(256) void pab_w_kernel(const float* __restrict__ Wp) {
    const int idx = blockIdx.x * 256 + threadIdx.x;
    const int k = idx & 255, n = idx >> 8;
    g_Wth[((k >> 6) * 4 + (n >> 6)) * 4096 + (k & 63) * 64 + (n & 63)] =
        __half_as_ushort(__float2half_rn(Wp[n * 256 + k]));
}

// ---------------------------------------------------------------------------
// Kernel 3: fused LN + u = A@xn (3-term fp16, in-place) + out = u@Wh (2-term)
//           + rs*bp.  One CTA = 2 windows (128 tokens), 8 warps.
// ---------------------------------------------------------------------------
__global__ __launch_bounds__(256, 1)
void pab_main_kernel(const float* __restrict__ x,
                     const float* __restrict__ gamma,
                     const float* __restrict__ beta,
                     const float* __restrict__ bp,
                     float* __restrict__ out) {
    extern __shared__ __align__(16) char smb[];
    const unsigned smu = smem_u32(smb);

    const int tid = threadIdx.x;
    const int lane = tid & 31, wid = tid >> 5;
    const int rem = blockIdx.x & 255;         // fi*4 + wi
    const int pair = blockIdx.x >> 8;         // 0..3
    const int fi = rem >> 2, wi = rem & 3;
    int wb[2];
#pragma unroll
    for (int w = 0; w < 2; ++w)
        wb[w] = (((pair * 2 + w) * 256 + fi * 4) * 64 + wi * 16) * ED;

    // ---- setup: bp, rsA, A_w (hi/lo) into smem ----
    ((float*)(smb + OFF_BP))[tid] = bp[tid];
    if (tid < 64) ((float*)(smb + OFF_RS))[tid] = g_rsA[rem * 64 + tid];
    for (int j = tid; j < 1024; j += 256) {
        const int hl = j >> 9, jj = j & 511;
        const uint4 v = ((const uint4*)(hl ? g_Al : g_Ah))[rem * 512 + jj];
        *(uint4*)(smb + OFF_A + hl * 9216 + (jj >> 3) * 144 + (jj & 7) * 16) = v;
    }

    // ---- LayerNorm -> xn hi/lo (padded row-major fp16) ----
    {
        float gr[8], br[8];
#pragma unroll
        for (int u = 0; u < 8; ++u) { gr[u] = gamma[lane * 8 + u]; br[u] = beta[lane * 8 + u]; }
        for (int r = 0; r < 16; ++r) {
            const int m = wid * 16 + r;
            const int win = m >> 6, l = m & 63;
            const float* xr = x + wb[win] + ((l >> 4) * 64 + (l & 15)) * ED;
            float4 a4 = *(const float4*)(xr + lane * 8);
            float4 b4 = *(const float4*)(xr + lane * 8 + 4);
            float v[8] = {a4.x, a4.y, a4.z, a4.w, b4.x, b4.y, b4.z, b4.w};
            float s = 0.f, s2 = 0.f;
#pragma unroll
            for (int u = 0; u < 8; ++u) { s += v[u]; s2 = fmaf(v[u], v[u], s2); }
#pragma unroll
            for (int o = 16; o > 0; o >>= 1) {
                s += __shfl_xor_sync(0xffffffffu, s, o);
                s2 += __shfl_xor_sync(0xffffffffu, s2, o);
            }
            const float mu = s * (1.f / 256.f);
            const float var = fmaf(-mu, mu, s2 * (1.f / 256.f));
            const float rstd = rsqrtf(var + 1e-5f);
            unsigned hh[8], ll[8];
#pragma unroll
            for (int u = 0; u < 8; ++u) {
                const float xn = (v[u] - mu) * rstd * gr[u] + br[u];
                unsigned short h, l2;
                split_f16(xn, h, l2);
                hh[u] = h; ll[u] = l2;
            }
            uint4 ph, pl;
            ph.x = hh[0] | (hh[1] << 16); ph.y = hh[2] | (hh[3] << 16);
            ph.z = hh[4] | (hh[5] << 16); ph.w = hh[6] | (hh[7] << 16);
            pl.x = ll[0] | (ll[1] << 16); pl.y = ll[2] | (ll[3] << 16);
            pl.z = ll[4] | (ll[5] << 16); pl.w = ll[6] | (ll[7] << 16);
            *(uint4*)(smb + OFF_XH + m * XROW + lane * 16) = ph;
            *(uint4*)(smb + OFF_XL + m * XROW + lane * 16) = pl;
        }
    }
    __syncthreads();

    // ---- Phase B: u[p][e] = sum_q A[p][q]*xn[q][e], 3-term, in-place by chunk ----
    const int w = wid >> 2, mb = wid & 3;
    const int lr = lane & 15, lc = lane >> 4;
    for (int nc = 0; nc < 4; ++nc) {
        float acc[8][4];
#pragma unroll
        for (int f = 0; f < 8; ++f)
#pragma unroll
            for (int j = 0; j < 4; ++j) acc[f][j] = 0.f;

#pragma unroll
        for (int ks = 0; ks < 4; ++ks) {
            unsigned Ah[4], Al[4];
            const unsigned aoff = (unsigned)((mb * 16 + lr) * 144 + (ks * 16 + lc * 8) * 2);
            ldsm4(Ah, smu + OFF_A + aoff);
            ldsm4(Al, smu + OFF_A + 9216u + aoff);
            const unsigned brow = (unsigned)((w * 64 + ks * 16 + lr) * XROW);
#pragma unroll
            for (int f4 = 0; f4 < 4; ++f4) {
                const unsigned bcol = (unsigned)((nc * 64 + f4 * 16 + lc * 8) * 2);
                unsigned Bh[4], Bl[4];
                ldsm4t(Bh, smu + OFF_XH + brow + bcol);
                ldsm4t(Bl, smu + OFF_XL + brow + bcol);
                mma16816(acc[2 * f4],     Ah, Bh);
                mma16816(acc[2 * f4],     Al, Bh);
                mma16816(acc[2 * f4],     Ah, Bl);
                mma16816(acc[2 * f4 + 1], Ah, Bh + 2);
                mma16816(acc[2 * f4 + 1], Al, Bh + 2);
                mma16816(acc[2 * f4 + 1], Ah, Bl + 2);
            }
        }
        __syncthreads();   // all reads of chunk nc done -> safe to overwrite
        const int r0 = w * 64 + mb * 16 + (lane >> 2);
#pragma unroll
        for (int f = 0; f < 8; ++f) {
            const int c = nc * 64 + f * 8 + (lane & 3) * 2;
            unsigned short h0, l0, h1, l1;
            split_f16(acc[f][0], h0, l0); split_f16(acc[f][1], h1, l1);
            *(unsigned*)(smb + OFF_XH + r0 * XROW + c * 2) = (unsigned)h0 | ((unsigned)h1 << 16);
            *(unsigned*)(smb + OFF_XL + r0 * XROW + c * 2) = (unsigned)l0 | ((unsigned)l1 << 16);
            split_f16(acc[f][2], h0, l0); split_f16(acc[f][3], h1, l1);
            *(unsigned*)(smb + OFF_XH + (r0 + 8) * XROW + c * 2) = (unsigned)h0 | ((unsigned)h1 << 16);
            *(unsigned*)(smb + OFF_XL + (r0 + 8) * XROW + c * 2) = (unsigned)l0 | ((unsigned)l1 << 16);
        }
    }

    // ---- Phase C: out[m][n] = sum_k (uh+ul)[m][k] * Wh[k][n] + rs[m]*bp[n] ----
    const float* bps = (const float*)(smb + OFF_BP);
    const float* rss = (const float*)(smb + OFF_RS);
    float acc[8][4];
    uint4 th[2];
    {   // prefetch tile 0 (kt=0, nc=0)
        const uint4* gh = (const uint4*)(g_Wth);
        th[0] = gh[tid]; th[1] = gh[tid + 256];
    }
    for (int i = 0; i < 16; ++i) {
        const int kt = i & 3, nc = i >> 2;
        __syncthreads();      // previous tile consumed (or phase B writes done)
        {
            const int j0 = tid, j1 = tid + 256;
            *(uint4*)(smb + OFF_WT + (j0 >> 3) * 144 + (j0 & 7) * 16) = th[0];
            *(uint4*)(smb + OFF_WT + (j1 >> 3) * 144 + (j1 & 7) * 16) = th[1];
        }
        if (i < 15) {
            const int ii = i + 1;
            const int base = (((ii & 3) * 4 + (ii >> 2)) * 4096) >> 3;   // uint4 index
            const uint4* gh = (const uint4*)(g_Wth);
            th[0] = gh[base + tid]; th[1] = gh[base + tid + 256];
        }
        __syncthreads();      // tile in smem
        if (kt == 0) {
#pragma unroll
            for (int f = 0; f < 8; ++f)
#pragma unroll
                for (int j = 0; j < 4; ++j) acc[f][j] = 0.f;
        }
#pragma unroll
        for (int ks = 0; ks < 4; ++ks) {
            unsigned Uh[4], Ul[4];
            const unsigned aoff = (unsigned)((wid * 16 + lr) * XROW + (kt * 64 + ks * 16 + lc * 8) * 2);
            ldsm4(Uh, smu + OFF_XH + aoff);
            ldsm4(Ul, smu + OFF_XL + aoff);
            const unsigned wrow = (unsigned)((ks * 16 + lr) * 144);
#pragma unroll
            for (int f4 = 0; f4 < 4; ++f4) {
                unsigned Bh[4];
                ldsm4t(Bh, smu + OFF_WT + wrow + (unsigned)((f4 * 16 + lc * 8) * 2));
                mma16816(acc[2 * f4],     Uh, Bh);
                mma16816(acc[2 * f4],     Ul, Bh);
                mma16816(acc[2 * f4 + 1], Uh, Bh + 2);
                mma16816(acc[2 * f4 + 1], Ul, Bh + 2);
            }
        }
        if (kt == 3) {   // epilogue for this n-chunk: direct global store
            const int m0 = wid * 16 + (lane >> 2);
#pragma unroll
            for (int f = 0; f < 8; ++f) {
                const int c = nc * 64 + f * 8 + (lane & 3) * 2;
                const float b0 = bps[c], b1 = bps[c + 1];
#pragma unroll
                for (int half = 0; half < 2; ++half) {
                    const int m = m0 + half * 8;
                    const int win = m >> 6, l = m & 63;
                    const float rs = rss[l];
                    float2 v;
                    v.x = acc[f][half * 2 + 0] + rs * b0;
                    v.y = acc[f][half * 2 + 1] + rs * b1;
                    *(float2*)(out + wb[win] + ((l >> 4) * 64 + (l & 15)) * ED + c) = v;
                }
            }
        }
    }
}

// ---------------------------------------------------------------------------
extern "C" void kernel_launch(void* const* d_in, const int* in_sizes, int n_in,
                              void* d_out, int out_size) {
    const float* x     = (const float*)d_in[0];
    const float* gamma = (const float*)d_in[1];
    const float* beta  = (const float*)d_in[2];
    const float* Wp    = (const float*)d_in[3];
    const float* bp    = (const float*)d_in[4];
    const float* eb    = (const float*)d_in[5];
    const float* deg   = (const float*)d_in[6];
    float* out = (float*)d_out;

    cudaFuncSetAttribute(pab_main_kernel,
                         cudaFuncAttributeMaxDynamicSharedMemorySize, (int)SMEM_BYTES);

    pab_a_kernel<<<512, 256>>>(deg, eb);
    pab_w_kernel<<<256, 256>>>(Wp);
    pab_main_kernel<<<1024, 256, SMEM_BYTES>>>(x, gamma, beta, bp, out);
}

// round 6
// speedup vs baseline: 2.7316x; 1.0955x over previous
#include <cuda_runtime.h>
#include <cuda_fp16.h>

#define ED 256

// ---- main-kernel smem layout (bytes). x rows: 256 + 8 pad = 264 fp16 = 528B ----
#define XROW 528u
#define OFF_XH 0u              // u/xn hi: 64 x 264 fp16 = 33792
#define OFF_XL 33792u          // lo
#define OFF_A  67584u          // A_w hi (9216) + lo (9216); 64 x 72 fp16 rows
#define OFF_WT 86016u          // Wt tile hi: 64 x 72 fp16 = 9216
#define OFF_BP 95232u          // 256 f32
#define OFF_RS 96256u          // 64 f32
#define SMEM_BYTES 96512u      // x2 CTAs = 193K <= 228K/SM

// ---- global scratch ----
__device__ __align__(16) unsigned short g_Ah[256 * 4096];
__device__ __align__(16) unsigned short g_Al[256 * 4096];
__device__ __align__(16) unsigned short g_Wth[65536];  // blocked (kt*4+nc) 64x64 fp16
__device__ float g_rsA[256 * 64];

// ---------------------------------------------------------------------------
__device__ __forceinline__ unsigned smem_u32(const void* p) {
    unsigned a;
    asm("{ .reg .u64 t; cvta.to.shared.u64 t, %1; cvt.u32.u64 %0, t; }" : "=r"(a) : "l"(p));
    return a;
}
__device__ __forceinline__ void ldsm4(unsigned r[4], unsigned a) {
    asm volatile("ldmatrix.sync.aligned.m8n8.x4.shared.b16 {%0,%1,%2,%3}, [%4];"
                 : "=r"(r[0]), "=r"(r[1]), "=r"(r[2]), "=r"(r[3]) : "r"(a));
}
__device__ __forceinline__ void ldsm4t(unsigned r[4], unsigned a) {
    asm volatile("ldmatrix.sync.aligned.m8n8.x4.trans.shared.b16 {%0,%1,%2,%3}, [%4];"
                 : "=r"(r[0]), "=r"(r[1]), "=r"(r[2]), "=r"(r[3]) : "r"(a));
}
__device__ __forceinline__ void mma16816(float d[4], const unsigned a[4], const unsigned b[2]) {
    asm volatile("mma.sync.aligned.m16n8k16.row.col.f32.f16.f16.f32 "
                 "{%0,%1,%2,%3}, {%4,%5,%6,%7}, {%8,%9}, {%0,%1,%2,%3};"
                 : "+f"(d[0]), "+f"(d[1]), "+f"(d[2]), "+f"(d[3])
                 : "r"(a[0]), "r"(a[1]), "r"(a[2]), "r"(a[3]), "r"(b[0]), "r"(b[1]));
}
__device__ __forceinline__ void split_f16(float v, unsigned short& h, unsigned short& l) {
    __half hh = __float2half_rn(v);
    __half ll = __float2half_rn(v - __half2float(hh));
    h = __half_as_ushort(hh);
    l = __half_as_ushort(ll);
}
__device__ __forceinline__ unsigned pack_split2(float a, float b, unsigned& lo) {
    unsigned short h0, l0, h1, l1;
    split_f16(a, h0, l0); split_f16(b, h1, l1);
    lo = (unsigned)l0 | ((unsigned)l1 << 16);
    return (unsigned)h0 | ((unsigned)h1 << 16);
}

// ---------------------------------------------------------------------------
// Kernel 1: A[w] = deg[w] @ eb[w] via 3-term fp16 mma -> fp16 hi/lo + rowsums.
// grid 256 (one window), 128 threads (4 warps).
// ---------------------------------------------------------------------------
__global__ __launch_bounds__(128) void pab_a_kernel(const float* __restrict__ deg,
                                                    const float* __restrict__ eb) {
    __shared__ __align__(16) unsigned short dh[64 * 72], dl[64 * 72];
    __shared__ __align__(16) unsigned short eh[64 * 72], el[64 * 72];
    const int w = blockIdx.x, tid = threadIdx.x;
    const int lane = tid & 31, wid = tid >> 5;
    const int lr = lane & 15, lc = lane >> 4;

    // load + split deg/eb (64x64 fp32 each) into fp16 hi/lo (72-stride rows)
    for (int j = tid; j < 1024; j += 128) {
        const int row = j >> 4, c4 = (j & 15) * 4;
        float4 v = ((const float4*)(deg + w * 4096))[j];
        unsigned lo0, lo1;
        unsigned hi0 = pack_split2(v.x, v.y, lo0);
        unsigned hi1 = pack_split2(v.z, v.w, lo1);
        *(uint2*)(dh + row * 72 + c4) = make_uint2(hi0, hi1);
        *(uint2*)(dl + row * 72 + c4) = make_uint2(lo0, lo1);
        v = ((const float4*)(eb + w * 4096))[j];
        hi0 = pack_split2(v.x, v.y, lo0);
        hi1 = pack_split2(v.z, v.w, lo1);
        *(uint2*)(eh + row * 72 + c4) = make_uint2(hi0, hi1);
        *(uint2*)(el + row * 72 + c4) = make_uint2(lo0, lo1);
    }
    __syncthreads();

    const unsigned sdh = smem_u32(dh), sdl = smem_u32(dl);
    const unsigned seh = smem_u32(eh), sel = smem_u32(el);
    float acc[8][4];
#pragma unroll
    for (int f = 0; f < 8; ++f)
#pragma unroll
        for (int j = 0; j < 4; ++j) acc[f][j] = 0.f;
#pragma unroll
    for (int ks = 0; ks < 4; ++ks) {
        unsigned Dh[4], Dl[4];
        const unsigned aoff = (unsigned)((wid * 16 + lr) * 144 + (ks * 16 + lc * 8) * 2);
        ldsm4(Dh, sdh + aoff);
        ldsm4(Dl, sdl + aoff);
        const unsigned brow = (unsigned)((ks * 16 + lr) * 144);
#pragma unroll
        for (int f4 = 0; f4 < 4; ++f4) {
            unsigned Eh[4], El[4];
            const unsigned boff = brow + (unsigned)((f4 * 16 + lc * 8) * 2);
            ldsm4t(Eh, seh + boff);
            ldsm4t(El, sel + boff);
            mma16816(acc[2 * f4],     Dh, Eh);
            mma16816(acc[2 * f4],     Dl, Eh);
            mma16816(acc[2 * f4],     Dh, El);
            mma16816(acc[2 * f4 + 1], Dh, Eh + 2);
            mma16816(acc[2 * f4 + 1], Dl, Eh + 2);
            mma16816(acc[2 * f4 + 1], Dh, El + 2);
        }
    }
    // rowsums
    float rs0 = 0.f, rs1 = 0.f;
#pragma unroll
    for (int f = 0; f < 8; ++f) {
        rs0 += acc[f][0] + acc[f][1];
        rs1 += acc[f][2] + acc[f][3];
    }
    rs0 += __shfl_xor_sync(0xffffffffu, rs0, 1); rs0 += __shfl_xor_sync(0xffffffffu, rs0, 2);
    rs1 += __shfl_xor_sync(0xffffffffu, rs1, 1); rs1 += __shfl_xor_sync(0xffffffffu, rs1, 2);
    const int r0 = wid * 16 + (lane >> 2);
    if ((lane & 3) == 0) {
        g_rsA[w * 64 + r0] = rs0;
        g_rsA[w * 64 + r0 + 8] = rs1;
    }
    // store hi/lo
#pragma unroll
    for (int f = 0; f < 8; ++f) {
        const int c = f * 8 + (lane & 3) * 2;
        unsigned lo;
        unsigned hi = pack_split2(acc[f][0], acc[f][1], lo);
        *(unsigned*)(g_Ah + w * 4096 + r0 * 64 + c) = hi;
        *(unsigned*)(g_Al + w * 4096 + r0 * 64 + c) = lo;
        hi = pack_split2(acc[f][2], acc[f][3], lo);
        *(unsigned*)(g_Ah + w * 4096 + (r0 + 8) * 64 + c) = hi;
        *(unsigned*)(g_Al + w * 4096 + (r0 + 8) * 64 + c) = lo;
    }
}

// ---------------------------------------------------------------------------
// Kernel 2: Wt[k][n] = fp16(Wp[n][k]), blocked into 16 tiles of 64x64 (kt*4+nc).
// ---------------------------------------------------------------------------
__global__ __launch_bounds__(256) void pab_w_kernel(const float* __restrict__ Wp) {
    const int idx = blockIdx.x * 256 + threadIdx.x;
    const int k = idx & 255, n = idx >> 8;
    g_Wth[((k >> 6) * 4 + (n >> 6)) * 4096 + (k & 63) * 64 + (n & 63)] =
        __half_as_ushort(__float2half_rn(Wp[n * 256 + k]));
}

// ---------------------------------------------------------------------------
// Kernel 3: fused LN + u = A@xn (3-term, in-place) + out = (uh+ul)@Wh + rs*bp.
// ONE window per CTA: 128 threads, 4 warps, grid 2048, 2 CTAs/SM.
// ---------------------------------------------------------------------------
__global__ __launch_bounds__(128, 2)
void pab_main_kernel(const float* __restrict__ x,
                     const float* __restrict__ gamma,
                     const float* __restrict__ beta,
                     const float* __restrict__ bp,
                     float* __restrict__ out) {
    extern __shared__ __align__(16) char smb[];
    const unsigned smu = smem_u32(smb);

    const int tid = threadIdx.x;
    const int lane = tid & 31, wid = tid >> 5;
    const int rem = blockIdx.x & 255;         // fi*4 + wi
    const int b = blockIdx.x >> 8;            // 0..7
    const int fi = rem >> 2, wi = rem & 3;
    const int wb = ((b * 256 + fi * 4) * 64 + wi * 16) * ED;

    // ---- setup: bp, rsA, A_w (hi/lo) into smem ----
    ((float*)(smb + OFF_BP))[tid] = bp[tid];
    ((float*)(smb + OFF_BP))[tid + 128] = bp[tid + 128];
    if (tid < 64) ((float*)(smb + OFF_RS))[tid] = g_rsA[rem * 64 + tid];
    for (int j = tid; j < 1024; j += 128) {
        const int hl = j >> 9, jj = j & 511;
        const uint4 v = ((const uint4*)(hl ? g_Al : g_Ah))[rem * 512 + jj];
        *(uint4*)(smb + OFF_A + hl * 9216 + (jj >> 3) * 144 + (jj & 7) * 16) = v;
    }

    // ---- LayerNorm -> xn hi/lo (padded row-major fp16), 16 rows per warp ----
    {
        float gr[8], br[8];
#pragma unroll
        for (int u = 0; u < 8; ++u) { gr[u] = gamma[lane * 8 + u]; br[u] = beta[lane * 8 + u]; }
        for (int r = 0; r < 16; ++r) {
            const int l = wid * 16 + r;
            const float* xr = x + wb + ((l >> 4) * 64 + (l & 15)) * ED;
            float4 a4 = *(const float4*)(xr + lane * 8);
            float4 b4 = *(const float4*)(xr + lane * 8 + 4);
            float v[8] = {a4.x, a4.y, a4.z, a4.w, b4.x, b4.y, b4.z, b4.w};
            float s = 0.f, s2 = 0.f;
#pragma unroll
            for (int u = 0; u < 8; ++u) { s += v[u]; s2 = fmaf(v[u], v[u], s2); }
#pragma unroll
            for (int o = 16; o > 0; o >>= 1) {
                s += __shfl_xor_sync(0xffffffffu, s, o);
                s2 += __shfl_xor_sync(0xffffffffu, s2, o);
            }
            const float mu = s * (1.f / 256.f);
            const float var = fmaf(-mu, mu, s2 * (1.f / 256.f));
            const float rstd = rsqrtf(var + 1e-5f);
            uint4 ph, pl;
            unsigned lo;
            float xn0 = (v[0] - mu) * rstd * gr[0] + br[0];
            float xn1 = (v[1] - mu) * rstd * gr[1] + br[1];
            ph.x = pack_split2(xn0, xn1, lo); pl.x = lo;
            xn0 = (v[2] - mu) * rstd * gr[2] + br[2];
            xn1 = (v[3] - mu) * rstd * gr[3] + br[3];
            ph.y = pack_split2(xn0, xn1, lo); pl.y = lo;
            xn0 = (v[4] - mu) * rstd * gr[4] + br[4];
            xn1 = (v[5] - mu) * rstd * gr[5] + br[5];
            ph.z = pack_split2(xn0, xn1, lo); pl.z = lo;
            xn0 = (v[6] - mu) * rstd * gr[6] + br[6];
            xn1 = (v[7] - mu) * rstd * gr[7] + br[7];
            ph.w = pack_split2(xn0, xn1, lo); pl.w = lo;
            *(uint4*)(smb + OFF_XH + l * XROW + lane * 16) = ph;
            *(uint4*)(smb + OFF_XL + l * XROW + lane * 16) = pl;
        }
    }
    __syncthreads();

    // ---- Phase B: u[p][e] = sum_q A[p][q]*xn[q][e], 3-term, in-place by chunk ----
    const int lr = lane & 15, lc = lane >> 4;
    for (int nc = 0; nc < 4; ++nc) {
        float acc[8][4];
#pragma unroll
        for (int f = 0; f < 8; ++f)
#pragma unroll
            for (int j = 0; j < 4; ++j) acc[f][j] = 0.f;

#pragma unroll
        for (int ks = 0; ks < 4; ++ks) {
            unsigned Ah[4], Al[4];
            const unsigned aoff = (unsigned)((wid * 16 + lr) * 144 + (ks * 16 + lc * 8) * 2);
            ldsm4(Ah, smu + OFF_A + aoff);
            ldsm4(Al, smu + OFF_A + 9216u + aoff);
            const unsigned brow = (unsigned)((ks * 16 + lr) * XROW);
#pragma unroll
            for (int f4 = 0; f4 < 4; ++f4) {
                const unsigned bcol = (unsigned)((nc * 64 + f4 * 16 + lc * 8) * 2);
                unsigned Bh[4], Bl[4];
                ldsm4t(Bh, smu + OFF_XH + brow + bcol);
                ldsm4t(Bl, smu + OFF_XL + brow + bcol);
                mma16816(acc[2 * f4],     Ah, Bh);
                mma16816(acc[2 * f4],     Al, Bh);
                mma16816(acc[2 * f4],     Ah, Bl);
                mma16816(acc[2 * f4 + 1], Ah, Bh + 2);
                mma16816(acc[2 * f4 + 1], Al, Bh + 2);
                mma16816(acc[2 * f4 + 1], Ah, Bl + 2);
            }
        }
        __syncthreads();   // all reads of chunk nc done -> safe to overwrite
        const int r0 = wid * 16 + (lane >> 2);
#pragma unroll
        for (int f = 0; f < 8; ++f) {
            const int c = nc * 64 + f * 8 + (lane & 3) * 2;
            unsigned lo;
            unsigned hi = pack_split2(acc[f][0], acc[f][1], lo);
            *(unsigned*)(smb + OFF_XH + r0 * XROW + c * 2) = hi;
            *(unsigned*)(smb + OFF_XL + r0 * XROW + c * 2) = lo;
            hi = pack_split2(acc[f][2], acc[f][3], lo);
            *(unsigned*)(smb + OFF_XH + (r0 + 8) * XROW + c * 2) = hi;
            *(unsigned*)(smb + OFF_XL + (r0 + 8) * XROW + c * 2) = lo;
        }
    }

    // ---- Phase C: out[m][n] = sum_k (uh+ul)[m][k] * Wh[k][n] + rs[m]*bp[n] ----
    const float* bps = (const float*)(smb + OFF_BP);
    const float* rss = (const float*)(smb + OFF_RS);
    float acc[8][4];
    uint4 th[4];
    {   // prefetch tile 0 (kt=0, nc=0): 512 uint4 over 128 threads
        const uint4* gh = (const uint4*)(g_Wth);
        th[0] = gh[tid]; th[1] = gh[tid + 128]; th[2] = gh[tid + 256]; th[3] = gh[tid + 384];
    }
    for (int i = 0; i < 16; ++i) {
        const int kt = i & 3, nc = i >> 2;
        __syncthreads();      // previous tile consumed (or phase B writes done)
#pragma unroll
        for (int u = 0; u < 4; ++u) {
            const int j = tid + u * 128;
            *(uint4*)(smb + OFF_WT + (j >> 3) * 144 + (j & 7) * 16) = th[u];
        }
        if (i < 15) {
            const int ii = i + 1;
            const int base = ((ii & 3) * 4 + (ii >> 2)) * 512;   // uint4 index
            const uint4* gh = (const uint4*)(g_Wth);
            th[0] = gh[base + tid]; th[1] = gh[base + tid + 128];
            th[2] = gh[base + tid + 256]; th[3] = gh[base + tid + 384];
        }
        __syncthreads();      // tile in smem
        if (kt == 0) {
#pragma unroll
            for (int f = 0; f < 8; ++f)
#pragma unroll
                for (int j = 0; j < 4; ++j) acc[f][j] = 0.f;
        }
#pragma unroll
        for (int ks = 0; ks < 4; ++ks) {
            unsigned Uh[4], Ul[4];
            const unsigned aoff = (unsigned)((wid * 16 + lr) * XROW + (kt * 64 + ks * 16 + lc * 8) * 2);
            ldsm4(Uh, smu + OFF_XH + aoff);
            ldsm4(Ul, smu + OFF_XL + aoff);
            const unsigned wrow = (unsigned)((ks * 16 + lr) * 144);
#pragma unroll
            for (int f4 = 0; f4 < 4; ++f4) {
                unsigned Bh[4];
                ldsm4t(Bh, smu + OFF_WT + wrow + (unsigned)((f4 * 16 + lc * 8) * 2));
                mma16816(acc[2 * f4],     Uh, Bh);
                mma16816(acc[2 * f4],     Ul, Bh);
                mma16816(acc[2 * f4 + 1], Uh, Bh + 2);
                mma16816(acc[2 * f4 + 1], Ul, Bh + 2);
            }
        }
        if (kt == 3) {   // epilogue for this n-chunk: direct global store
            const int m0 = wid * 16 + (lane >> 2);
#pragma unroll
            for (int f = 0; f < 8; ++f) {
                const int c = nc * 64 + f * 8 + (lane & 3) * 2;
                const float b0 = bps[c], b1 = bps[c + 1];
#pragma unroll
                for (int half = 0; half < 2; ++half) {
                    const int l = m0 + half * 8;
                    const float rs = rss[l];
                    float2 v;
                    v.x = acc[f][half * 2 + 0] + rs * b0;
                    v.y = acc[f][half * 2 + 1] + rs * b1;
                    *(float2*)(out + wb + ((l >> 4) * 64 + (l & 15)) * ED + c) = v;
                }
            }
        }
    }
}

// ---------------------------------------------------------------------------
extern "C" void kernel_launch(void* const* d_in, const int* in_sizes, int n_in,
                              void* d_out, int out_size) {
    const float* x     = (const float*)d_in[0];
    const float* gamma = (const float*)d_in[1];
    const float* beta  = (const float*)d_in[2];
    const float* Wp    = (const float*)d_in[3];
    const float* bp    = (const float*)d_in[4];
    const float* eb    = (const float*)d_in[5];
    const float* deg   = (const float*)d_in[6];
    float* out = (float*)d_out;

    cudaFuncSetAttribute(pab_main_kernel,
                         cudaFuncAttributeMaxDynamicSharedMemorySize, (int)SMEM_BYTES);

    pab_a_kernel<<<256, 128>>>(deg, eb);
    pab_w_kernel<<<256, 256>>>(Wp);
    pab_main_kernel<<<2048, 128, SMEM_BYTES>>>(x, gamma, beta, bp, out);
}

// round 7
// speedup vs baseline: 3.6634x; 1.3411x over previous
#include <cuda_runtime.h>
#include <cuda_fp16.h>

#define ED 256

// ---- main-kernel smem layout (bytes). x rows: 256 + 8 pad = 264 fp16 = 528B ----
#define XROW 528u
#define OFF_XH 0u              // u/xn hi: 64 x 264 fp16 = 33792
#define OFF_XL 33792u          // lo
#define OFF_A  67584u          // A_w hi (9216) + lo (9216); 64 x 72 fp16 rows
#define OFF_WT 86016u          // TWO Wt tiles (one per n-group): 2 x 9216
#define OFF_BP 104448u         // 256 f32
#define OFF_RS 105472u         // 64 f32
#define SMEM_BYTES 105728u     // x2 CTAs = 211456 <= 228K/SM

// ---- global scratch ----
__device__ __align__(16) unsigned short g_Ah[256 * 4096];
__device__ __align__(16) unsigned short g_Al[256 * 4096];
__device__ __align__(16) unsigned short g_Wth[65536];  // blocked (kt*4+nc) 64x64 fp16
__device__ float g_rsA[256 * 64];

// ---------------------------------------------------------------------------
__device__ __forceinline__ unsigned smem_u32(const void* p) {
    unsigned a;
    asm("{ .reg .u64 t; cvta.to.shared.u64 t, %1; cvt.u32.u64 %0, t; }" : "=r"(a) : "l"(p));
    return a;
}
__device__ __forceinline__ void ldsm4(unsigned r[4], unsigned a) {
    asm volatile("ldmatrix.sync.aligned.m8n8.x4.shared.b16 {%0,%1,%2,%3}, [%4];"
                 : "=r"(r[0]), "=r"(r[1]), "=r"(r[2]), "=r"(r[3]) : "r"(a));
}
__device__ __forceinline__ void ldsm4t(unsigned r[4], unsigned a) {
    asm volatile("ldmatrix.sync.aligned.m8n8.x4.trans.shared.b16 {%0,%1,%2,%3}, [%4];"
                 : "=r"(r[0]), "=r"(r[1]), "=r"(r[2]), "=r"(r[3]) : "r"(a));
}
__device__ __forceinline__ void mma16816(float d[4], const unsigned a[4], const unsigned b[2]) {
    asm volatile("mma.sync.aligned.m16n8k16.row.col.f32.f16.f16.f32 "
                 "{%0,%1,%2,%3}, {%4,%5,%6,%7}, {%8,%9}, {%0,%1,%2,%3};"
                 : "+f"(d[0]), "+f"(d[1]), "+f"(d[2]), "+f"(d[3])
                 : "r"(a[0]), "r"(a[1]), "r"(a[2]), "r"(a[3]), "r"(b[0]), "r"(b[1]));
}
__device__ __forceinline__ void split_f16(float v, unsigned short& h, unsigned short& l) {
    __half hh = __float2half_rn(v);
    __half ll = __float2half_rn(v - __half2float(hh));
    h = __half_as_ushort(hh);
    l = __half_as_ushort(ll);
}
__device__ __forceinline__ unsigned pack_split2(float a, float b, unsigned& lo) {
    unsigned short h0, l0, h1, l1;
    split_f16(a, h0, l0); split_f16(b, h1, l1);
    lo = (unsigned)l0 | ((unsigned)l1 << 16);
    return (unsigned)h0 | ((unsigned)h1 << 16);
}

// ---------------------------------------------------------------------------
// Kernel 1: A[w] = deg[w] @ eb[w] via 3-term fp16 mma -> fp16 hi/lo + rowsums.
// ---------------------------------------------------------------------------
__global__ __launch_bounds__(128) void pab_a_kernel(const float* __restrict__ deg,
                                                    const float* __restrict__ eb) {
    __shared__ __align__(16) unsigned short dh[64 * 72], dl[64 * 72];
    __shared__ __align__(16) unsigned short eh[64 * 72], el[64 * 72];
    const int w = blockIdx.x, tid = threadIdx.x;
    const int lane = tid & 31, wid = tid >> 5;
    const int lr = lane & 15, lc = lane >> 4;

    for (int j = tid; j < 1024; j += 128) {
        const int row = j >> 4, c4 = (j & 15) * 4;
        float4 v = ((const float4*)(deg + w * 4096))[j];
        unsigned lo0, lo1;
        unsigned hi0 = pack_split2(v.x, v.y, lo0);
        unsigned hi1 = pack_split2(v.z, v.w, lo1);
        *(uint2*)(dh + row * 72 + c4) = make_uint2(hi0, hi1);
        *(uint2*)(dl + row * 72 + c4) = make_uint2(lo0, lo1);
        v = ((const float4*)(eb + w * 4096))[j];
        hi0 = pack_split2(v.x, v.y, lo0);
        hi1 = pack_split2(v.z, v.w, lo1);
        *(uint2*)(eh + row * 72 + c4) = make_uint2(hi0, hi1);
        *(uint2*)(el + row * 72 + c4) = make_uint2(lo0, lo1);
    }
    __syncthreads();

    const unsigned sdh = smem_u32(dh), sdl = smem_u32(dl);
    const unsigned seh = smem_u32(eh), sel = smem_u32(el);
    float acc[8][4];
#pragma unroll
    for (int f = 0; f < 8; ++f)
#pragma unroll
        for (int j = 0; j < 4; ++j) acc[f][j] = 0.f;
#pragma unroll
    for (int ks = 0; ks < 4; ++ks) {
        unsigned Dh[4], Dl[4];
        const unsigned aoff = (unsigned)((wid * 16 + lr) * 144 + (ks * 16 + lc * 8) * 2);
        ldsm4(Dh, sdh + aoff);
        ldsm4(Dl, sdl + aoff);
        const unsigned brow = (unsigned)((ks * 16 + lr) * 144);
#pragma unroll
        for (int f4 = 0; f4 < 4; ++f4) {
            unsigned Eh[4], El[4];
            const unsigned boff = brow + (unsigned)((f4 * 16 + lc * 8) * 2);
            ldsm4t(Eh, seh + boff);
            ldsm4t(El, sel + boff);
            mma16816(acc[2 * f4],     Dh, Eh);
            mma16816(acc[2 * f4],     Dl, Eh);
            mma16816(acc[2 * f4],     Dh, El);
            mma16816(acc[2 * f4 + 1], Dh, Eh + 2);
            mma16816(acc[2 * f4 + 1], Dl, Eh + 2);
            mma16816(acc[2 * f4 + 1], Dh, El + 2);
        }
    }
    float rs0 = 0.f, rs1 = 0.f;
#pragma unroll
    for (int f = 0; f < 8; ++f) {
        rs0 += acc[f][0] + acc[f][1];
        rs1 += acc[f][2] + acc[f][3];
    }
    rs0 += __shfl_xor_sync(0xffffffffu, rs0, 1); rs0 += __shfl_xor_sync(0xffffffffu, rs0, 2);
    rs1 += __shfl_xor_sync(0xffffffffu, rs1, 1); rs1 += __shfl_xor_sync(0xffffffffu, rs1, 2);
    const int r0 = wid * 16 + (lane >> 2);
    if ((lane & 3) == 0) {
        g_rsA[w * 64 + r0] = rs0;
        g_rsA[w * 64 + r0 + 8] = rs1;
    }
#pragma unroll
    for (int f = 0; f < 8; ++f) {
        const int c = f * 8 + (lane & 3) * 2;
        unsigned lo;
        unsigned hi = pack_split2(acc[f][0], acc[f][1], lo);
        *(unsigned*)(g_Ah + w * 4096 + r0 * 64 + c) = hi;
        *(unsigned*)(g_Al + w * 4096 + r0 * 64 + c) = lo;
        hi = pack_split2(acc[f][2], acc[f][3], lo);
        *(unsigned*)(g_Ah + w * 4096 + (r0 + 8) * 64 + c) = hi;
        *(unsigned*)(g_Al + w * 4096 + (r0 + 8) * 64 + c) = lo;
    }
}

// ---------------------------------------------------------------------------
// Kernel 2: Wt[k][n] = fp16(Wp[n][k]), blocked into 16 tiles of 64x64 (kt*4+nc).
// ---------------------------------------------------------------------------
__global__ __launch_bounds__(256) void pab_w_kernel(const float* __restrict__ Wp) {
    const int idx = blockIdx.x * 256 + threadIdx.x;
    const int k = idx & 255, n = idx >> 8;
    g_Wth[((k >> 6) * 4 + (n >> 6)) * 4096 + (k & 63) * 64 + (n & 63)] =
        __half_as_ushort(__float2half_rn(Wp[n * 256 + k]));
}

// ---------------------------------------------------------------------------
// Kernel 3: fused LN + u = A@xn (3-term, in-place) + out = (uh+ul)@Wh + rs*bp.
// ONE window per CTA, 256 threads (8 warps), 2 CTAs/SM -> 4 warps/SMSP.
// Warp (wid&3) = 16-row block;  group g = wid>>2 = n-half (2 of 4 n-chunks).
// ---------------------------------------------------------------------------
__global__ __launch_bounds__(256, 2)
void pab_main_kernel(const float* __restrict__ x,
                     const float* __restrict__ gamma,
                     const float* __restrict__ beta,
                     const float* __restrict__ bp,
                     float* __restrict__ out) {
    extern __shared__ __align__(16) char smb[];
    const unsigned smu = smem_u32(smb);

    const int tid = threadIdx.x;
    const int lane = tid & 31, wid = tid >> 5;
    const int g = wid >> 2;                   // n-group
    const int mw = wid & 3;                   // 16-row block
    const int rem = blockIdx.x & 255;         // fi*4 + wi
    const int b = blockIdx.x >> 8;            // 0..7
    const int fi = rem >> 2, wi = rem & 3;
    const int wb = ((b * 256 + fi * 4) * 64 + wi * 16) * ED;

    // ---- setup: bp, rsA, A_w (hi/lo) into smem ----
    ((float*)(smb + OFF_BP))[tid] = bp[tid];
    if (tid < 64) ((float*)(smb + OFF_RS))[tid] = g_rsA[rem * 64 + tid];
#pragma unroll
    for (int u = 0; u < 4; ++u) {
        const int j = tid + u * 256;
        const int hl = j >> 9, jj = j & 511;
        const uint4 v = ((const uint4*)(hl ? g_Al : g_Ah))[rem * 512 + jj];
        *(uint4*)(smb + OFF_A + hl * 9216 + (jj >> 3) * 144 + (jj & 7) * 16) = v;
    }

    // ---- LayerNorm -> xn hi/lo (padded row-major fp16), 8 rows per warp ----
    {
        float gr[8], br[8];
#pragma unroll
        for (int u = 0; u < 8; ++u) { gr[u] = gamma[lane * 8 + u]; br[u] = beta[lane * 8 + u]; }
#pragma unroll
        for (int r = 0; r < 8; ++r) {
            const int l = wid * 8 + r;
            const float* xr = x + wb + ((l >> 4) * 64 + (l & 15)) * ED;
            float4 a4 = *(const float4*)(xr + lane * 8);
            float4 b4 = *(const float4*)(xr + lane * 8 + 4);
            float v[8] = {a4.x, a4.y, a4.z, a4.w, b4.x, b4.y, b4.z, b4.w};
            float s = 0.f, s2 = 0.f;
#pragma unroll
            for (int u = 0; u < 8; ++u) { s += v[u]; s2 = fmaf(v[u], v[u], s2); }
#pragma unroll
            for (int o = 16; o > 0; o >>= 1) {
                s += __shfl_xor_sync(0xffffffffu, s, o);
                s2 += __shfl_xor_sync(0xffffffffu, s2, o);
            }
            const float mu = s * (1.f / 256.f);
            const float var = fmaf(-mu, mu, s2 * (1.f / 256.f));
            const float rstd = rsqrtf(var + 1e-5f);
            uint4 ph, pl;
            unsigned lo;
            float xn0 = (v[0] - mu) * rstd * gr[0] + br[0];
            float xn1 = (v[1] - mu) * rstd * gr[1] + br[1];
            ph.x = pack_split2(xn0, xn1, lo); pl.x = lo;
            xn0 = (v[2] - mu) * rstd * gr[2] + br[2];
            xn1 = (v[3] - mu) * rstd * gr[3] + br[3];
            ph.y = pack_split2(xn0, xn1, lo); pl.y = lo;
            xn0 = (v[4] - mu) * rstd * gr[4] + br[4];
            xn1 = (v[5] - mu) * rstd * gr[5] + br[5];
            ph.z = pack_split2(xn0, xn1, lo); pl.z = lo;
            xn0 = (v[6] - mu) * rstd * gr[6] + br[6];
            xn1 = (v[7] - mu) * rstd * gr[7] + br[7];
            ph.w = pack_split2(xn0, xn1, lo); pl.w = lo;
            *(uint4*)(smb + OFF_XH + l * XROW + lane * 16) = ph;
            *(uint4*)(smb + OFF_XL + l * XROW + lane * 16) = pl;
        }
    }
    __syncthreads();

    // ---- Phase B: u[p][e] = sum_q A[p][q]*xn[q][e], 3-term, in-place.
    //      Group g handles n-chunks {2g, 2g+1}; rows = mw*16..+15. ----
    const int lr = lane & 15, lc = lane >> 4;
    for (int jj = 0; jj < 2; ++jj) {
        const int nc = g * 2 + jj;
        float acc[8][4];
#pragma unroll
        for (int f = 0; f < 8; ++f)
#pragma unroll
            for (int j = 0; j < 4; ++j) acc[f][j] = 0.f;

#pragma unroll
        for (int ks = 0; ks < 4; ++ks) {
            unsigned Ah[4], Al[4];
            const unsigned aoff = (unsigned)((mw * 16 + lr) * 144 + (ks * 16 + lc * 8) * 2);
            ldsm4(Ah, smu + OFF_A + aoff);
            ldsm4(Al, smu + OFF_A + 9216u + aoff);
            const unsigned brow = (unsigned)((ks * 16 + lr) * XROW);
#pragma unroll
            for (int f4 = 0; f4 < 4; ++f4) {
                const unsigned bcol = (unsigned)((nc * 64 + f4 * 16 + lc * 8) * 2);
                unsigned Bh[4], Bl[4];
                ldsm4t(Bh, smu + OFF_XH + brow + bcol);
                ldsm4t(Bl, smu + OFF_XL + brow + bcol);
                mma16816(acc[2 * f4],     Ah, Bh);
                mma16816(acc[2 * f4],     Al, Bh);
                mma16816(acc[2 * f4],     Ah, Bl);
                mma16816(acc[2 * f4 + 1], Ah, Bh + 2);
                mma16816(acc[2 * f4 + 1], Al, Bh + 2);
                mma16816(acc[2 * f4 + 1], Ah, Bl + 2);
            }
        }
        __syncthreads();   // all reads of this chunk's columns done -> overwrite
        const int r0 = mw * 16 + (lane >> 2);
#pragma unroll
        for (int f = 0; f < 8; ++f) {
            const int c = nc * 64 + f * 8 + (lane & 3) * 2;
            unsigned lo;
            unsigned hi = pack_split2(acc[f][0], acc[f][1], lo);
            *(unsigned*)(smb + OFF_XH + r0 * XROW + c * 2) = hi;
            *(unsigned*)(smb + OFF_XL + r0 * XROW + c * 2) = lo;
            hi = pack_split2(acc[f][2], acc[f][3], lo);
            *(unsigned*)(smb + OFF_XH + (r0 + 8) * XROW + c * 2) = hi;
            *(unsigned*)(smb + OFF_XL + (r0 + 8) * XROW + c * 2) = lo;
        }
    }

    // ---- Phase C: out[m][n] = sum_k (uh+ul)[m][k] * Wh[k][n] + rs[m]*bp[n].
    //      Group g handles n-chunks {2g, 2g+1}; two W tiles staged per iter. ----
    const float* bps = (const float*)(smb + OFF_BP);
    const float* rss = (const float*)(smb + OFF_RS);
    float acc[8][4];
    uint4 th[4];
    {   // prefetch iter 0 tiles: (kt=0, nc=0) and (kt=0, nc=2)
        const uint4* gh = (const uint4*)(g_Wth);
#pragma unroll
        for (int u = 0; u < 4; ++u) {
            const int j = tid + u * 256;
            const int t = j >> 9, within = j & 511;
            th[u] = gh[(t ? 2 * 512 : 0) + within];
        }
    }
    for (int j = 0; j < 2; ++j) {
        for (int kt = 0; kt < 4; ++kt) {
            const int i = j * 4 + kt;
            __syncthreads();      // previous tiles consumed (or phase B writes done)
#pragma unroll
            for (int u = 0; u < 4; ++u) {
                const int jj2 = tid + u * 256;
                const int t = jj2 >> 9, within = jj2 & 511;
                *(uint4*)(smb + OFF_WT + t * 9216 + (within >> 3) * 144 + (within & 7) * 16) = th[u];
            }
            if (i < 7) {
                const int inext = i + 1;
                const int jn = inext >> 2, ktn = inext & 3;
                const uint4* gh = (const uint4*)(g_Wth);
#pragma unroll
                for (int u = 0; u < 4; ++u) {
                    const int jj2 = tid + u * 256;
                    const int t = jj2 >> 9, within = jj2 & 511;
                    const int tile = ktn * 4 + jn + (t ? 2 : 0);
                    th[u] = gh[tile * 512 + within];
                }
            }
            __syncthreads();      // tiles in smem
            if (kt == 0) {
#pragma unroll
                for (int f = 0; f < 8; ++f)
#pragma unroll
                    for (int jr = 0; jr < 4; ++jr) acc[f][jr] = 0.f;
            }
#pragma unroll
            for (int ks = 0; ks < 4; ++ks) {
                unsigned Uh[4], Ul[4];
                const unsigned aoff =
                    (unsigned)((mw * 16 + lr) * XROW + (kt * 64 + ks * 16 + lc * 8) * 2);
                ldsm4(Uh, smu + OFF_XH + aoff);
                ldsm4(Ul, smu + OFF_XL + aoff);
                const unsigned wrow = (unsigned)(g * 9216 + (ks * 16 + lr) * 144);
#pragma unroll
                for (int f4 = 0; f4 < 4; ++f4) {
                    unsigned Bh[4];
                    ldsm4t(Bh, smu + OFF_WT + wrow + (unsigned)((f4 * 16 + lc * 8) * 2));
                    mma16816(acc[2 * f4],     Uh, Bh);
                    mma16816(acc[2 * f4],     Ul, Bh);
                    mma16816(acc[2 * f4 + 1], Uh, Bh + 2);
                    mma16816(acc[2 * f4 + 1], Ul, Bh + 2);
                }
            }
            if (kt == 3) {   // epilogue for this n-chunk: direct global store
                const int nc = g * 2 + j;
                const int m0 = mw * 16 + (lane >> 2);
#pragma unroll
                for (int f = 0; f < 8; ++f) {
                    const int c = nc * 64 + f * 8 + (lane & 3) * 2;
                    const float b0 = bps[c], b1 = bps[c + 1];
#pragma unroll
                    for (int half = 0; half < 2; ++half) {
                        const int l = m0 + half * 8;
                        const float rs = rss[l];
                        float2 v;
                        v.x = acc[f][half * 2 + 0] + rs * b0;
                        v.y = acc[f][half * 2 + 1] + rs * b1;
                        *(float2*)(out + wb + ((l >> 4) * 64 + (l & 15)) * ED + c) = v;
                    }
                }
            }
        }
    }
}

// ---------------------------------------------------------------------------
extern "C" void kernel_launch(void* const* d_in, const int* in_sizes, int n_in,
                              void* d_out, int out_size) {
    const float* x     = (const float*)d_in[0];
    const float* gamma = (const float*)d_in[1];
    const float* beta  = (const float*)d_in[2];
    const float* Wp    = (const float*)d_in[3];
    const float* bp    = (const float*)d_in[4];
    const float* eb    = (const float*)d_in[5];
    const float* deg   = (const float*)d_in[6];
    float* out = (float*)d_out;

    cudaFuncSetAttribute(pab_main_kernel,
                         cudaFuncAttributeMaxDynamicSharedMemorySize, (int)SMEM_BYTES);

    pab_a_kernel<<<256, 128>>>(deg, eb);
    pab_w_kernel<<<256, 256>>>(Wp);
    pab_main_kernel<<<2048, 256, SMEM_BYTES>>>(x, gamma, beta, bp, out);
}

// round 11
// speedup vs baseline: 4.2728x; 1.1664x over previous
#include <cuda_runtime.h>
#include <cuda_fp16.h>

#define ED 256

// ---- main-kernel smem layout (bytes). x rows: 256 + 8 pad = 264 fp16 = 528B ----
#define XROW 528u
#define OFF_XH 0u              // u/xn hi: 64 x 264 fp16 = 33792
#define OFF_XL 33792u          // xn lo; dead after Phase B -> WT buffer 1
#define OFF_A  67584u          // A_w hi (9216) + lo (9216); 64 x 72 fp16 rows
#define OFF_WT 86016u          // WT buffer 0: two tiles (one per n-group): 2 x 9216
#define OFF_BP 104448u         // 256 f32
#define OFF_RS 105472u         // 64 f32
#define SMEM_BYTES 105728u     // x2 CTAs = 211456 <= 228K/SM

// ---- global scratch ----
__device__ __align__(16) unsigned short g_Ah[256 * 4096];
__device__ __align__(16) unsigned short g_Al[256 * 4096];
__device__ __align__(16) unsigned short g_Wth[65536];  // blocked (kt*4+nc) 64x64 fp16
__device__ float g_rsA[256 * 64];

// ---------------------------------------------------------------------------
__device__ __forceinline__ unsigned smem_u32(const void* p) {
    unsigned a;
    asm("{ .reg .u64 t; cvta.to.shared.u64 t, %1; cvt.u32.u64 %0, t; }" : "=r"(a) : "l"(p));
    return a;
}
__device__ __forceinline__ void ldsm4(unsigned r[4], unsigned a) {
    asm volatile("ldmatrix.sync.aligned.m8n8.x4.shared.b16 {%0,%1,%2,%3}, [%4];"
                 : "=r"(r[0]), "=r"(r[1]), "=r"(r[2]), "=r"(r[3]) : "r"(a));
}
__device__ __forceinline__ void ldsm4t(unsigned r[4], unsigned a) {
    asm volatile("ldmatrix.sync.aligned.m8n8.x4.trans.shared.b16 {%0,%1,%2,%3}, [%4];"
                 : "=r"(r[0]), "=r"(r[1]), "=r"(r[2]), "=r"(r[3]) : "r"(a));
}
__device__ __forceinline__ void mma16816(float d[4], const unsigned a[4], const unsigned b[2]) {
    asm volatile("mma.sync.aligned.m16n8k16.row.col.f32.f16.f16.f32 "
                 "{%0,%1,%2,%3}, {%4,%5,%6,%7}, {%8,%9}, {%0,%1,%2,%3};"
                 : "+f"(d[0]), "+f"(d[1]), "+f"(d[2]), "+f"(d[3])
                 : "r"(a[0]), "r"(a[1]), "r"(a[2]), "r"(a[3]), "r"(b[0]), "r"(b[1]));
}
__device__ __forceinline__ void split_f16(float v, unsigned short& h, unsigned short& l) {
    __half hh = __float2half_rn(v);
    __half ll = __float2half_rn(v - __half2float(hh));
    h = __half_as_ushort(hh);
    l = __half_as_ushort(ll);
}
__device__ __forceinline__ unsigned pack_split2(float a, float b, unsigned& lo) {
    unsigned short h0, l0, h1, l1;
    split_f16(a, h0, l0); split_f16(b, h1, l1);
    lo = (unsigned)l0 | ((unsigned)l1 << 16);
    return (unsigned)h0 | ((unsigned)h1 << 16);
}

// ---------------------------------------------------------------------------
// Prep kernel.  Blocks [0,256): A[w] = deg[w] @ eb[w] via 3-term fp16 mma,
// store fp16 hi/lo + rowsums.  Blocks [256,768): Wt split/transpose/block.
// ---------------------------------------------------------------------------
__global__ __launch_bounds__(128) void pab_prep_kernel(const float* __restrict__ deg,
                                                       const float* __restrict__ eb,
                                                       const float* __restrict__ Wp) {
    if (blockIdx.x >= 256) {
        const int idx = (blockIdx.x - 256) * 128 + threadIdx.x;  // 65536
        const int k = idx & 255, n = idx >> 8;
        g_Wth[((k >> 6) * 4 + (n >> 6)) * 4096 + (k & 63) * 64 + (n & 63)] =
            __half_as_ushort(__float2half_rn(Wp[n * 256 + k]));
        return;
    }
    __shared__ __align__(16) unsigned short dh[64 * 72], dl[64 * 72];
    __shared__ __align__(16) unsigned short eh[64 * 72], el[64 * 72];
    const int w = blockIdx.x, tid = threadIdx.x;
    const int lane = tid & 31, wid = tid >> 5;
    const int lr = lane & 15, lc = lane >> 4;

    for (int j = tid; j < 1024; j += 128) {
        const int row = j >> 4, c4 = (j & 15) * 4;
        float4 v = ((const float4*)(deg + w * 4096))[j];
        unsigned lo0, lo1;
        unsigned hi0 = pack_split2(v.x, v.y, lo0);
        unsigned hi1 = pack_split2(v.z, v.w, lo1);
        *(uint2*)(dh + row * 72 + c4) = make_uint2(hi0, hi1);
        *(uint2*)(dl + row * 72 + c4) = make_uint2(lo0, lo1);
        v = ((const float4*)(eb + w * 4096))[j];
        hi0 = pack_split2(v.x, v.y, lo0);
        hi1 = pack_split2(v.z, v.w, lo1);
        *(uint2*)(eh + row * 72 + c4) = make_uint2(hi0, hi1);
        *(uint2*)(el + row * 72 + c4) = make_uint2(lo0, lo1);
    }
    __syncthreads();

    const unsigned sdh = smem_u32(dh), sdl = smem_u32(dl);
    const unsigned seh = smem_u32(eh), sel = smem_u32(el);
    float acc[8][4];
#pragma unroll
    for (int f = 0; f < 8; ++f)
#pragma unroll
        for (int j = 0; j < 4; ++j) acc[f][j] = 0.f;
#pragma unroll
    for (int ks = 0; ks < 4; ++ks) {
        unsigned Dh[4], Dl[4];
        const unsigned aoff = (unsigned)((wid * 16 + lr) * 144 + (ks * 16 + lc * 8) * 2);
        ldsm4(Dh, sdh + aoff);
        ldsm4(Dl, sdl + aoff);
        const unsigned brow = (unsigned)((ks * 16 + lr) * 144);
#pragma unroll
        for (int f4 = 0; f4 < 4; ++f4) {
            unsigned Eh[4], El[4];
            const unsigned boff = brow + (unsigned)((f4 * 16 + lc * 8) * 2);
            ldsm4t(Eh, seh + boff);
            ldsm4t(El, sel + boff);
            mma16816(acc[2 * f4],     Dh, Eh);
            mma16816(acc[2 * f4],     Dl, Eh);
            mma16816(acc[2 * f4],     Dh, El);
            mma16816(acc[2 * f4 + 1], Dh, Eh + 2);
            mma16816(acc[2 * f4 + 1], Dl, Eh + 2);
            mma16816(acc[2 * f4 + 1], Dh, El + 2);
        }
    }
    float rs0 = 0.f, rs1 = 0.f;
#pragma unroll
    for (int f = 0; f < 8; ++f) {
        rs0 += acc[f][0] + acc[f][1];
        rs1 += acc[f][2] + acc[f][3];
    }
    rs0 += __shfl_xor_sync(0xffffffffu, rs0, 1); rs0 += __shfl_xor_sync(0xffffffffu, rs0, 2);
    rs1 += __shfl_xor_sync(0xffffffffu, rs1, 1); rs1 += __shfl_xor_sync(0xffffffffu, rs1, 2);
    const int r0 = wid * 16 + (lane >> 2);
    if ((lane & 3) == 0) {
        g_rsA[w * 64 + r0] = rs0;
        g_rsA[w * 64 + r0 + 8] = rs1;
    }
#pragma unroll
    for (int f = 0; f < 8; ++f) {
        const int c = f * 8 + (lane & 3) * 2;
        unsigned lo;
        unsigned hi = pack_split2(acc[f][0], acc[f][1], lo);
        *(unsigned*)(g_Ah + w * 4096 + r0 * 64 + c) = hi;
        *(unsigned*)(g_Al + w * 4096 + r0 * 64 + c) = lo;
        hi = pack_split2(acc[f][2], acc[f][3], lo);
        *(unsigned*)(g_Ah + w * 4096 + (r0 + 8) * 64 + c) = hi;
        *(unsigned*)(g_Al + w * 4096 + (r0 + 8) * 64 + c) = lo;
    }
}

// ---------------------------------------------------------------------------
// Main kernel: fused LN + u = A@xn (3-term, in-place, hi-only output)
//            + out = uh@Wh + rs*bp (single-term, double-buffered W tiles).
// ONE window per CTA, 256 threads (8 warps), 2 CTAs/SM -> 4 warps/SMSP.
// Warp (wid&3) = 16-row block;  group g = wid>>2 = n-half.
// ---------------------------------------------------------------------------
__global__ __launch_bounds__(256, 2)
void pab_main_kernel(const float* __restrict__ x,
                     const float* __restrict__ gamma,
                     const float* __restrict__ beta,
                     const float* __restrict__ bp,
                     float* __restrict__ out) {
    extern __shared__ __align__(16) char smb[];
    const unsigned smu = smem_u32(smb);

    const int tid = threadIdx.x;
    const int lane = tid & 31, wid = tid >> 5;
    const int g = wid >> 2;                   // n-group
    const int mw = wid & 3;                   // 16-row block
    const int rem = blockIdx.x & 255;         // fi*4 + wi
    const int b = blockIdx.x >> 8;            // 0..7
    const int fi = rem >> 2, wi = rem & 3;
    const int wb = ((b * 256 + fi * 4) * 64 + wi * 16) * ED;

    // ---- setup: bp, rsA, A_w (hi/lo) into smem ----
    ((float*)(smb + OFF_BP))[tid] = bp[tid];
    if (tid < 64) ((float*)(smb + OFF_RS))[tid] = g_rsA[rem * 64 + tid];
#pragma unroll
    for (int u = 0; u < 4; ++u) {
        const int j = tid + u * 256;
        const int hl = j >> 9, jj = j & 511;
        const uint4 v = ((const uint4*)(hl ? g_Al : g_Ah))[rem * 512 + jj];
        *(uint4*)(smb + OFF_A + hl * 9216 + (jj >> 3) * 144 + (jj & 7) * 16) = v;
    }

    // ---- LayerNorm -> xn hi/lo (padded row-major fp16), 8 rows per warp ----
    {
        float gr[8], br[8];
#pragma unroll
        for (int u = 0; u < 8; ++u) { gr[u] = gamma[lane * 8 + u]; br[u] = beta[lane * 8 + u]; }
#pragma unroll
        for (int r = 0; r < 8; ++r) {
            const int l = wid * 8 + r;
            const float* xr = x + wb + ((l >> 4) * 64 + (l & 15)) * ED;
            float4 a4 = *(const float4*)(xr + lane * 8);
            float4 b4 = *(const float4*)(xr + lane * 8 + 4);
            float v[8] = {a4.x, a4.y, a4.z, a4.w, b4.x, b4.y, b4.z, b4.w};
            float s = 0.f, s2 = 0.f;
#pragma unroll
            for (int u = 0; u < 8; ++u) { s += v[u]; s2 = fmaf(v[u], v[u], s2); }
#pragma unroll
            for (int o = 16; o > 0; o >>= 1) {
                s += __shfl_xor_sync(0xffffffffu, s, o);
                s2 += __shfl_xor_sync(0xffffffffu, s2, o);
            }
            const float mu = s * (1.f / 256.f);
            const float var = fmaf(-mu, mu, s2 * (1.f / 256.f));
            const float rstd = rsqrtf(var + 1e-5f);
            uint4 ph, pl;
            unsigned lo;
            float xn0 = (v[0] - mu) * rstd * gr[0] + br[0];
            float xn1 = (v[1] - mu) * rstd * gr[1] + br[1];
            ph.x = pack_split2(xn0, xn1, lo); pl.x = lo;
            xn0 = (v[2] - mu) * rstd * gr[2] + br[2];
            xn1 = (v[3] - mu) * rstd * gr[3] + br[3];
            ph.y = pack_split2(xn0, xn1, lo); pl.y = lo;
            xn0 = (v[4] - mu) * rstd * gr[4] + br[4];
            xn1 = (v[5] - mu) * rstd * gr[5] + br[5];
            ph.z = pack_split2(xn0, xn1, lo); pl.z = lo;
            xn0 = (v[6] - mu) * rstd * gr[6] + br[6];
            xn1 = (v[7] - mu) * rstd * gr[7] + br[7];
            ph.w = pack_split2(xn0, xn1, lo); pl.w = lo;
            *(uint4*)(smb + OFF_XH + l * XROW + lane * 16) = ph;
            *(uint4*)(smb + OFF_XL + l * XROW + lane * 16) = pl;
        }
    }
    __syncthreads();

    // ---- Phase B: u[p][e] = sum_q A[p][q]*xn[q][e], 3-term, in-place (hi out).
    //      Group g handles n-chunks {2g, 2g+1}; rows = mw*16..+15. ----
    const int lr = lane & 15, lc = lane >> 4;
    for (int jj = 0; jj < 2; ++jj) {
        const int nc = g * 2 + jj;
        float acc[8][4];
#pragma unroll
        for (int f = 0; f < 8; ++f)
#pragma unroll
            for (int j = 0; j < 4; ++j) acc[f][j] = 0.f;

#pragma unroll
        for (int ks = 0; ks < 4; ++ks) {
            unsigned Ah[4], Al[4];
            const unsigned aoff = (unsigned)((mw * 16 + lr) * 144 + (ks * 16 + lc * 8) * 2);
            ldsm4(Ah, smu + OFF_A + aoff);
            ldsm4(Al, smu + OFF_A + 9216u + aoff);
            const unsigned brow = (unsigned)((ks * 16 + lr) * XROW);
#pragma unroll
            for (int f4 = 0; f4 < 4; ++f4) {
                const unsigned bcol = (unsigned)((nc * 64 + f4 * 16 + lc * 8) * 2);
                unsigned Bh[4], Bl[4];
                ldsm4t(Bh, smu + OFF_XH + brow + bcol);
                ldsm4t(Bl, smu + OFF_XL + brow + bcol);
                mma16816(acc[2 * f4],     Ah, Bh);
                mma16816(acc[2 * f4],     Al, Bh);
                mma16816(acc[2 * f4],     Ah, Bl);
                mma16816(acc[2 * f4 + 1], Ah, Bh + 2);
                mma16816(acc[2 * f4 + 1], Al, Bh + 2);
                mma16816(acc[2 * f4 + 1], Ah, Bl + 2);
            }
        }
        __syncthreads();   // all reads of this chunk's columns done -> overwrite
        const int r0 = mw * 16 + (lane >> 2);
#pragma unroll
        for (int f = 0; f < 8; ++f) {
            const int c = nc * 64 + f * 8 + (lane & 3) * 2;
            unsigned lo;
            unsigned hi = pack_split2(acc[f][0], acc[f][1], lo);
            *(unsigned*)(smb + OFF_XH + r0 * XROW + c * 2) = hi;
            hi = pack_split2(acc[f][2], acc[f][3], lo);
            *(unsigned*)(smb + OFF_XH + (r0 + 8) * XROW + c * 2) = hi;
        }
    }

    // ---- Phase C: out[m][n] = sum_k uh[m][k] * Wh[k][n] + rs[m]*bp[n].
    //      Single-term; W tiles double-buffered (buf1 reuses dead XL region);
    //      ONE barrier per iteration. ----
    const float* bps = (const float*)(smb + OFF_BP);
    const float* rss = (const float*)(smb + OFF_RS);
    float acc[8][4];
    uint4 th[4];
    {   // prefetch iter 0 tiles: (kt=0, nc=0) and (kt=0, nc=2)
        const uint4* gh = (const uint4*)(g_Wth);
#pragma unroll
        for (int u = 0; u < 4; ++u) {
            const int j = tid + u * 256;
            const int t = j >> 9, within = j & 511;
            th[u] = gh[(t ? 2 * 512 : 0) + within];
        }
    }
    for (int i = 0; i < 8; ++i) {
        const int j = i >> 2, kt = i & 3;
        const unsigned bufbase = (i & 1) ? OFF_XL : OFF_WT;
        // store prefetched tiles into this iteration's buffer
#pragma unroll
        for (int u = 0; u < 4; ++u) {
            const int jj2 = tid + u * 256;
            const int t = jj2 >> 9, within = jj2 & 511;
            *(uint4*)(smb + bufbase + t * 9216 + (within >> 3) * 144 + (within & 7) * 16) = th[u];
        }
        if (i < 7) {   // prefetch next iteration's tiles
            const int inext = i + 1;
            const int jn = inext >> 2, ktn = inext & 3;
            const uint4* gh = (const uint4*)(g_Wth);
#pragma unroll
            for (int u = 0; u < 4; ++u) {
                const int jj2 = tid + u * 256;
                const int t = jj2 >> 9, within = jj2 & 511;
                const int tile = ktn * 4 + jn + (t ? 2 : 0);
                th[u] = gh[tile * 512 + within];
            }
        }
        __syncthreads();   // buffer stored by all (also orders vs Phase B / prev reads)
        if (kt == 0) {
#pragma unroll
            for (int f = 0; f < 8; ++f)
#pragma unroll
                for (int jr = 0; jr < 4; ++jr) acc[f][jr] = 0.f;
        }
#pragma unroll
        for (int ks = 0; ks < 4; ++ks) {
            unsigned Uh[4];
            const unsigned aoff =
                (unsigned)((mw * 16 + lr) * XROW + (kt * 64 + ks * 16 + lc * 8) * 2);
            ldsm4(Uh, smu + OFF_XH + aoff);
            const unsigned wrow = bufbase + (unsigned)(g * 9216 + (ks * 16 + lr) * 144);
#pragma unroll
            for (int f4 = 0; f4 < 4; ++f4) {
                unsigned Bh[4];
                ldsm4t(Bh, smu + wrow + (unsigned)((f4 * 16 + lc * 8) * 2));
                mma16816(acc[2 * f4],     Uh, Bh);
                mma16816(acc[2 * f4 + 1], Uh, Bh + 2);
            }
        }
        if (kt == 3) {   // epilogue for this n-chunk: direct global store
            const int nc = g * 2 + j;
            const int m0 = mw * 16 + (lane >> 2);
#pragma unroll
            for (int f = 0; f < 8; ++f) {
                const int c = nc * 64 + f * 8 + (lane & 3) * 2;
                const float b0 = bps[c], b1 = bps[c + 1];
#pragma unroll
                for (int half = 0; half < 2; ++half) {
                    const int l = m0 + half * 8;
                    const float rs = rss[l];
                    float2 v;
                    v.x = acc[f][half * 2 + 0] + rs * b0;
                    v.y = acc[f][half * 2 + 1] + rs * b1;
                    *(float2*)(out + wb + ((l >> 4) * 64 + (l & 15)) * ED + c) = v;
                }
            }
        }
    }
}

// ---------------------------------------------------------------------------
extern "C" void kernel_launch(void* const* d_in, const int* in_sizes, int n_in,
                              void* d_out, int out_size) {
    const float* x     = (const float*)d_in[0];
    const float* gamma = (const float*)d_in[1];
    const float* beta  = (const float*)d_in[2];
    const float* Wp    = (const float*)d_in[3];
    const float* bp    = (const float*)d_in[4];
    const float* eb    = (const float*)d_in[5];
    const float* deg   = (const float*)d_in[6];
    float* out = (float*)d_out;

    cudaFuncSetAttribute(pab_main_kernel,
                         cudaFuncAttributeMaxDynamicSharedMemorySize, (int)SMEM_BYTES);

    pab_prep_kernel<<<768, 128>>>(deg, eb, Wp);
    pab_main_kernel<<<2048, 256, SMEM_BYTES>>>(x, gamma, beta, bp, out);
}

// round 12
// speedup vs baseline: 5.0009x; 1.1704x over previous
#include <cuda_runtime.h>
#include <cuda_fp16.h>

#define ED 256

// ---- main-kernel smem layout (bytes). x rows: 256 + 8 pad = 264 fp16 = 528B ----
#define XROW 528u
#define OFF_XH 0u              // u/xn hi: 64 x 264 fp16 = 33792
#define OFF_XL 33792u          // xn lo
#define OFF_A  67584u          // A_w hi (9216) + lo (9216); 64 x 72 fp16 rows
#define OFF_BP 86016u          // 256 f32
#define OFF_RS 87040u          // 64 f32
#define SMEM_BYTES 87296u      // x2 CTAs = 174592 <= 228K/SM

// ---- global scratch ----
__device__ __align__(16) unsigned short g_Ah[256 * 4096];
__device__ __align__(16) unsigned short g_Al[256 * 4096];
// W in mma-b-fragment-major order: block = (kt*4+nc)*16 + ks*4 + f4 (512B each),
// within block lane*16 + reg*4.  g_Wfrag[blk*128 + lane*4 + r].
__device__ __align__(16) unsigned g_Wfrag[32768];
__device__ float g_rsA[256 * 64];

// ---------------------------------------------------------------------------
__device__ __forceinline__ unsigned smem_u32(const void* p) {
    unsigned a;
    asm("{ .reg .u64 t; cvta.to.shared.u64 t, %1; cvt.u32.u64 %0, t; }" : "=r"(a) : "l"(p));
    return a;
}
__device__ __forceinline__ void ldsm4(unsigned r[4], unsigned a) {
    asm volatile("ldmatrix.sync.aligned.m8n8.x4.shared.b16 {%0,%1,%2,%3}, [%4];"
                 : "=r"(r[0]), "=r"(r[1]), "=r"(r[2]), "=r"(r[3]) : "r"(a));
}
__device__ __forceinline__ void ldsm4t(unsigned r[4], unsigned a) {
    asm volatile("ldmatrix.sync.aligned.m8n8.x4.trans.shared.b16 {%0,%1,%2,%3}, [%4];"
                 : "=r"(r[0]), "=r"(r[1]), "=r"(r[2]), "=r"(r[3]) : "r"(a));
}
__device__ __forceinline__ void mma16816(float d[4], const unsigned a[4], const unsigned b[2]) {
    asm volatile("mma.sync.aligned.m16n8k16.row.col.f32.f16.f16.f32 "
                 "{%0,%1,%2,%3}, {%4,%5,%6,%7}, {%8,%9}, {%0,%1,%2,%3};"
                 : "+f"(d[0]), "+f"(d[1]), "+f"(d[2]), "+f"(d[3])
                 : "r"(a[0]), "r"(a[1]), "r"(a[2]), "r"(a[3]), "r"(b[0]), "r"(b[1]));
}
__device__ __forceinline__ void split_f16(float v, unsigned short& h, unsigned short& l) {
    __half hh = __float2half_rn(v);
    __half ll = __float2half_rn(v - __half2float(hh));
    h = __half_as_ushort(hh);
    l = __half_as_ushort(ll);
}
__device__ __forceinline__ unsigned pack_split2(float a, float b, unsigned& lo) {
    unsigned short h0, l0, h1, l1;
    split_f16(a, h0, l0); split_f16(b, h1, l1);
    lo = (unsigned)l0 | ((unsigned)l1 << 16);
    return (unsigned)h0 | ((unsigned)h1 << 16);
}

// ---------------------------------------------------------------------------
// Prep kernel.  Blocks [0,256): A[w] = deg[w] @ eb[w] via 3-term fp16 mma,
// store fp16 hi/lo + rowsums.  Blocks [256,512): W -> fragment-major g_Wfrag.
// ---------------------------------------------------------------------------
__global__ __launch_bounds__(128) void pab_prep_kernel(const float* __restrict__ deg,
                                                       const float* __restrict__ eb,
                                                       const float* __restrict__ Wp) {
    if (blockIdx.x >= 256) {
        // one u32 (= f16x2, a k-pair) per thread: 32768 total
        const int idx = (blockIdx.x - 256) * 128 + threadIdx.x;
        const int r = idx & 3, l = (idx >> 2) & 31, blk = idx >> 7;
        const int f4 = blk & 3, ks = (blk >> 2) & 3, nc = (blk >> 4) & 3, kt = blk >> 6;
        const int k = kt * 64 + ks * 16 + (r & 1) * 8 + 2 * (l & 3);
        const int n = nc * 64 + f4 * 16 + ((r >> 1) & 1) * 8 + (l >> 2);
        // W[k][n] = Wp[n][k]; pack {W[k][n], W[k+1][n]}
        const unsigned short h0 = __half_as_ushort(__float2half_rn(Wp[n * 256 + k]));
        const unsigned short h1 = __half_as_ushort(__float2half_rn(Wp[n * 256 + k + 1]));
        g_Wfrag[idx] = (unsigned)h0 | ((unsigned)h1 << 16);
        return;
    }
    __shared__ __align__(16) unsigned short dh[64 * 72], dl[64 * 72];
    __shared__ __align__(16) unsigned short eh[64 * 72], el[64 * 72];
    const int w = blockIdx.x, tid = threadIdx.x;
    const int lane = tid & 31, wid = tid >> 5;
    const int lr = lane & 15, lc = lane >> 4;

    for (int j = tid; j < 1024; j += 128) {
        const int row = j >> 4, c4 = (j & 15) * 4;
        float4 v = ((const float4*)(deg + w * 4096))[j];
        unsigned lo0, lo1;
        unsigned hi0 = pack_split2(v.x, v.y, lo0);
        unsigned hi1 = pack_split2(v.z, v.w, lo1);
        *(uint2*)(dh + row * 72 + c4) = make_uint2(hi0, hi1);
        *(uint2*)(dl + row * 72 + c4) = make_uint2(lo0, lo1);
        v = ((const float4*)(eb + w * 4096))[j];
        hi0 = pack_split2(v.x, v.y, lo0);
        hi1 = pack_split2(v.z, v.w, lo1);
        *(uint2*)(eh + row * 72 + c4) = make_uint2(hi0, hi1);
        *(uint2*)(el + row * 72 + c4) = make_uint2(lo0, lo1);
    }
    __syncthreads();

    const unsigned sdh = smem_u32(dh), sdl = smem_u32(dl);
    const unsigned seh = smem_u32(eh), sel = smem_u32(el);
    float acc[8][4];
#pragma unroll
    for (int f = 0; f < 8; ++f)
#pragma unroll
        for (int j = 0; j < 4; ++j) acc[f][j] = 0.f;
#pragma unroll
    for (int ks = 0; ks < 4; ++ks) {
        unsigned Dh[4], Dl[4];
        const unsigned aoff = (unsigned)((wid * 16 + lr) * 144 + (ks * 16 + lc * 8) * 2);
        ldsm4(Dh, sdh + aoff);
        ldsm4(Dl, sdl + aoff);
        const unsigned brow = (unsigned)((ks * 16 + lr) * 144);
#pragma unroll
        for (int f4 = 0; f4 < 4; ++f4) {
            unsigned Eh[4], El[4];
            const unsigned boff = brow + (unsigned)((f4 * 16 + lc * 8) * 2);
            ldsm4t(Eh, seh + boff);
            ldsm4t(El, sel + boff);
            mma16816(acc[2 * f4],     Dh, Eh);
            mma16816(acc[2 * f4],     Dl, Eh);
            mma16816(acc[2 * f4],     Dh, El);
            mma16816(acc[2 * f4 + 1], Dh, Eh + 2);
            mma16816(acc[2 * f4 + 1], Dl, Eh + 2);
            mma16816(acc[2 * f4 + 1], Dh, El + 2);
        }
    }
    float rs0 = 0.f, rs1 = 0.f;
#pragma unroll
    for (int f = 0; f < 8; ++f) {
        rs0 += acc[f][0] + acc[f][1];
        rs1 += acc[f][2] + acc[f][3];
    }
    rs0 += __shfl_xor_sync(0xffffffffu, rs0, 1); rs0 += __shfl_xor_sync(0xffffffffu, rs0, 2);
    rs1 += __shfl_xor_sync(0xffffffffu, rs1, 1); rs1 += __shfl_xor_sync(0xffffffffu, rs1, 2);
    const int r0 = wid * 16 + (lane >> 2);
    if ((lane & 3) == 0) {
        g_rsA[w * 64 + r0] = rs0;
        g_rsA[w * 64 + r0 + 8] = rs1;
    }
#pragma unroll
    for (int f = 0; f < 8; ++f) {
        const int c = f * 8 + (lane & 3) * 2;
        unsigned lo;
        unsigned hi = pack_split2(acc[f][0], acc[f][1], lo);
        *(unsigned*)(g_Ah + w * 4096 + r0 * 64 + c) = hi;
        *(unsigned*)(g_Al + w * 4096 + r0 * 64 + c) = lo;
        hi = pack_split2(acc[f][2], acc[f][3], lo);
        *(unsigned*)(g_Ah + w * 4096 + (r0 + 8) * 64 + c) = hi;
        *(unsigned*)(g_Al + w * 4096 + (r0 + 8) * 64 + c) = lo;
    }
}

// ---------------------------------------------------------------------------
// Main kernel: fused LN + u = A@xn (3-term, in-place, hi out) +
//   out = uh@Wh + rs*bp, W fragments streamed by LDG from g_Wfrag (no smem,
//   no barriers in Phase C).  256 thr, 2 CTAs/SM, warp (wid&3)=rows, g=n-half.
// ---------------------------------------------------------------------------
__global__ __launch_bounds__(256, 2)
void pab_main_kernel(const float* __restrict__ x,
                     const float* __restrict__ gamma,
                     const float* __restrict__ beta,
                     const float* __restrict__ bp,
                     float* __restrict__ out) {
    extern __shared__ __align__(16) char smb[];
    const unsigned smu = smem_u32(smb);

    const int tid = threadIdx.x;
    const int lane = tid & 31, wid = tid >> 5;
    const int g = wid >> 2;                   // n-group
    const int mw = wid & 3;                   // 16-row block
    const int rem = blockIdx.x & 255;         // fi*4 + wi
    const int b = blockIdx.x >> 8;            // 0..7
    const int fi = rem >> 2, wi = rem & 3;
    const int wb = ((b * 256 + fi * 4) * 64 + wi * 16) * ED;

    // ---- setup: bp, rsA, A_w (hi/lo) into smem ----
    ((float*)(smb + OFF_BP))[tid] = bp[tid];
    if (tid < 64) ((float*)(smb + OFF_RS))[tid] = g_rsA[rem * 64 + tid];
#pragma unroll
    for (int u = 0; u < 4; ++u) {
        const int j = tid + u * 256;
        const int hl = j >> 9, jj = j & 511;
        const uint4 v = ((const uint4*)(hl ? g_Al : g_Ah))[rem * 512 + jj];
        *(uint4*)(smb + OFF_A + hl * 9216 + (jj >> 3) * 144 + (jj & 7) * 16) = v;
    }

    // ---- LayerNorm -> xn hi/lo (padded row-major fp16), 8 rows per warp ----
    {
        float gr[8], br[8];
#pragma unroll
        for (int u = 0; u < 8; ++u) { gr[u] = gamma[lane * 8 + u]; br[u] = beta[lane * 8 + u]; }
#pragma unroll
        for (int r = 0; r < 8; ++r) {
            const int l = wid * 8 + r;
            const float* xr = x + wb + ((l >> 4) * 64 + (l & 15)) * ED;
            float4 a4 = *(const float4*)(xr + lane * 8);
            float4 b4 = *(const float4*)(xr + lane * 8 + 4);
            float v[8] = {a4.x, a4.y, a4.z, a4.w, b4.x, b4.y, b4.z, b4.w};
            float s = 0.f, s2 = 0.f;
#pragma unroll
            for (int u = 0; u < 8; ++u) { s += v[u]; s2 = fmaf(v[u], v[u], s2); }
#pragma unroll
            for (int o = 16; o > 0; o >>= 1) {
                s += __shfl_xor_sync(0xffffffffu, s, o);
                s2 += __shfl_xor_sync(0xffffffffu, s2, o);
            }
            const float mu = s * (1.f / 256.f);
            const float var = fmaf(-mu, mu, s2 * (1.f / 256.f));
            const float rstd = rsqrtf(var + 1e-5f);
            uint4 ph, pl;
            unsigned lo;
            float xn0 = (v[0] - mu) * rstd * gr[0] + br[0];
            float xn1 = (v[1] - mu) * rstd * gr[1] + br[1];
            ph.x = pack_split2(xn0, xn1, lo); pl.x = lo;
            xn0 = (v[2] - mu) * rstd * gr[2] + br[2];
            xn1 = (v[3] - mu) * rstd * gr[3] + br[3];
            ph.y = pack_split2(xn0, xn1, lo); pl.y = lo;
            xn0 = (v[4] - mu) * rstd * gr[4] + br[4];
            xn1 = (v[5] - mu) * rstd * gr[5] + br[5];
            ph.z = pack_split2(xn0, xn1, lo); pl.z = lo;
            xn0 = (v[6] - mu) * rstd * gr[6] + br[6];
            xn1 = (v[7] - mu) * rstd * gr[7] + br[7];
            ph.w = pack_split2(xn0, xn1, lo); pl.w = lo;
            *(uint4*)(smb + OFF_XH + l * XROW + lane * 16) = ph;
            *(uint4*)(smb + OFF_XL + l * XROW + lane * 16) = pl;
        }
    }
    __syncthreads();

    // ---- Phase B: u[p][e] = sum_q A[p][q]*xn[q][e], 3-term, in-place (hi out).
    //      Group g handles n-chunks {2g, 2g+1}; rows = mw*16..+15. ----
    const int lr = lane & 15, lc = lane >> 4;
    for (int jj = 0; jj < 2; ++jj) {
        const int nc = g * 2 + jj;
        float acc[8][4];
#pragma unroll
        for (int f = 0; f < 8; ++f)
#pragma unroll
            for (int j = 0; j < 4; ++j) acc[f][j] = 0.f;

#pragma unroll
        for (int ks = 0; ks < 4; ++ks) {
            unsigned Ah[4], Al[4];
            const unsigned aoff = (unsigned)((mw * 16 + lr) * 144 + (ks * 16 + lc * 8) * 2);
            ldsm4(Ah, smu + OFF_A + aoff);
            ldsm4(Al, smu + OFF_A + 9216u + aoff);
            const unsigned brow = (unsigned)((ks * 16 + lr) * XROW);
#pragma unroll
            for (int f4 = 0; f4 < 4; ++f4) {
                const unsigned bcol = (unsigned)((nc * 64 + f4 * 16 + lc * 8) * 2);
                unsigned Bh[4], Bl[4];
                ldsm4t(Bh, smu + OFF_XH + brow + bcol);
                ldsm4t(Bl, smu + OFF_XL + brow + bcol);
                mma16816(acc[2 * f4],     Ah, Bh);
                mma16816(acc[2 * f4],     Al, Bh);
                mma16816(acc[2 * f4],     Ah, Bl);
                mma16816(acc[2 * f4 + 1], Ah, Bh + 2);
                mma16816(acc[2 * f4 + 1], Al, Bh + 2);
                mma16816(acc[2 * f4 + 1], Ah, Bl + 2);
            }
        }
        __syncthreads();   // all reads of this chunk's columns done -> overwrite
        const int r0 = mw * 16 + (lane >> 2);
#pragma unroll
        for (int f = 0; f < 8; ++f) {
            const int c = nc * 64 + f * 8 + (lane & 3) * 2;
            unsigned lo;
            unsigned hi = pack_split2(acc[f][0], acc[f][1], lo);
            *(unsigned*)(smb + OFF_XH + r0 * XROW + c * 2) = hi;
            hi = pack_split2(acc[f][2], acc[f][3], lo);
            *(unsigned*)(smb + OFF_XH + (r0 + 8) * XROW + c * 2) = hi;
        }
    }
    __syncthreads();       // U fully written (cross-group cols) before Phase C reads

    // ---- Phase C: out[m][n] = sum_k uh[m][k] * Wh[k][n] + rs[m]*bp[n].
    //      W b-fragments streamed via LDG from g_Wfrag; double-buffered per-ks
    //      prefetch; NO barriers, NO smem staging. ----
    const float* bps = (const float*)(smb + OFF_BP);
    const float* rss = (const float*)(smb + OFF_RS);
    for (int j = 0; j < 2; ++j) {
        const int nc = g * 2 + j;
        float acc[8][4];
#pragma unroll
        for (int f = 0; f < 8; ++f)
#pragma unroll
            for (int jr = 0; jr < 4; ++jr) acc[f][jr] = 0.f;

        unsigned Wf[2][16];
        {   // prefetch step 0: (kt=0, ks=0), 4 f4 blocks
            const unsigned* p = g_Wfrag + (nc * 16) * 128 + lane * 4;
            *(uint4*)&Wf[0][0]  = *(const uint4*)(p);
            *(uint4*)&Wf[0][4]  = *(const uint4*)(p + 128);
            *(uint4*)&Wf[0][8]  = *(const uint4*)(p + 256);
            *(uint4*)&Wf[0][12] = *(const uint4*)(p + 384);
        }
#pragma unroll
        for (int kt = 0; kt < 4; ++kt) {
#pragma unroll
            for (int ks = 0; ks < 4; ++ks) {
                const int step = kt * 4 + ks;
                const int pb = step & 1;
                if (step < 15) {   // prefetch next (kt,ks)
                    const int ns = step + 1;
                    const int nkt = ns >> 2, nks = ns & 3;
                    const unsigned* p =
                        g_Wfrag + (((nkt * 4 + nc) * 16 + nks * 4) * 128) + lane * 4;
                    *(uint4*)&Wf[pb ^ 1][0]  = *(const uint4*)(p);
                    *(uint4*)&Wf[pb ^ 1][4]  = *(const uint4*)(p + 128);
                    *(uint4*)&Wf[pb ^ 1][8]  = *(const uint4*)(p + 256);
                    *(uint4*)&Wf[pb ^ 1][12] = *(const uint4*)(p + 384);
                }
                unsigned Uh[4];
                const unsigned aoff =
                    (unsigned)((mw * 16 + lr) * XROW + (kt * 64 + ks * 16 + lc * 8) * 2);
                ldsm4(Uh, smu + OFF_XH + aoff);
                const unsigned* Wc = Wf[pb];
#pragma unroll
                for (int f4 = 0; f4 < 4; ++f4) {
                    mma16816(acc[2 * f4],     Uh, Wc + f4 * 4);
                    mma16816(acc[2 * f4 + 1], Uh, Wc + f4 * 4 + 2);
                }
            }
        }
        // epilogue for this n-chunk: direct global store
        const int m0 = mw * 16 + (lane >> 2);
#pragma unroll
        for (int f = 0; f < 8; ++f) {
            const int c = nc * 64 + f * 8 + (lane & 3) * 2;
            const float b0 = bps[c], b1 = bps[c + 1];
#pragma unroll
            for (int half = 0; half < 2; ++half) {
                const int l = m0 + half * 8;
                const float rs = rss[l];
                float2 v;
                v.x = acc[f][half * 2 + 0] + rs * b0;
                v.y = acc[f][half * 2 + 1] + rs * b1;
                *(float2*)(out + wb + ((l >> 4) * 64 + (l & 15)) * ED + c) = v;
            }
        }
    }
}

// ---------------------------------------------------------------------------
extern "C" void kernel_launch(void* const* d_in, const int* in_sizes, int n_in,
                              void* d_out, int out_size) {
    const float* x     = (const float*)d_in[0];
    const float* gamma = (const float*)d_in[1];
    const float* beta  = (const float*)d_in[2];
    const float* Wp    = (const float*)d_in[3];
    const float* bp    = (const float*)d_in[4];
    const float* eb    = (const float*)d_in[5];
    const float* deg   = (const float*)d_in[6];
    float* out = (float*)d_out;

    cudaFuncSetAttribute(pab_main_kernel,
                         cudaFuncAttributeMaxDynamicSharedMemorySize, (int)SMEM_BYTES);

    pab_prep_kernel<<<512, 128>>>(deg, eb, Wp);
    pab_main_kernel<<<2048, 256, SMEM_BYTES>>>(x, gamma, beta, bp, out);
}

// round 14
// speedup vs baseline: 5.8630x; 1.1724x over previous
#include <cuda_runtime.h>
#include <cuda_fp16.h>

#define ED 256

// ---- main-kernel smem layout (bytes). x rows: 256 + 8 pad = 264 fp16 = 528B ----
#define XROW 528u
#define OFF_XH 0u              // u/xn hi: 64 x 264 fp16 = 33792
#define OFF_A  33792u          // A_w hi (9216) + lo (9216); 64 x 72 fp16 rows
#define OFF_BP 52224u          // 256 f32
#define OFF_RS 53248u          // 64 f32
#define SMEM_BYTES 53504u      // x2 CTAs = 107008 <= 228K/SM

// ---- global scratch ----
__device__ __align__(16) unsigned short g_Ah[256 * 4096];
__device__ __align__(16) unsigned short g_Al[256 * 4096];
// W in mma-b-fragment-major order: block = (kt*4+nc64)*16 + ks*4 + f4 (512B each),
// within block lane*16 + reg*4.  g_Wfrag[blk*128 + lane*4 + r].
__device__ __align__(16) unsigned g_Wfrag[32768];
__device__ float g_rsA[256 * 64];

// ---------------------------------------------------------------------------
__device__ __forceinline__ unsigned smem_u32(const void* p) {
    unsigned a;
    asm("{ .reg .u64 t; cvta.to.shared.u64 t, %1; cvt.u32.u64 %0, t; }" : "=r"(a) : "l"(p));
    return a;
}
__device__ __forceinline__ void ldsm4(unsigned r[4], unsigned a) {
    asm volatile("ldmatrix.sync.aligned.m8n8.x4.shared.b16 {%0,%1,%2,%3}, [%4];"
                 : "=r"(r[0]), "=r"(r[1]), "=r"(r[2]), "=r"(r[3]) : "r"(a));
}
__device__ __forceinline__ void ldsm4t(unsigned r[4], unsigned a) {
    asm volatile("ldmatrix.sync.aligned.m8n8.x4.trans.shared.b16 {%0,%1,%2,%3}, [%4];"
                 : "=r"(r[0]), "=r"(r[1]), "=r"(r[2]), "=r"(r[3]) : "r"(a));
}
__device__ __forceinline__ void mma16816(float d[4], const unsigned a[4], const unsigned b[2]) {
    asm volatile("mma.sync.aligned.m16n8k16.row.col.f32.f16.f16.f32 "
                 "{%0,%1,%2,%3}, {%4,%5,%6,%7}, {%8,%9}, {%0,%1,%2,%3};"
                 : "+f"(d[0]), "+f"(d[1]), "+f"(d[2]), "+f"(d[3])
                 : "r"(a[0]), "r"(a[1]), "r"(a[2]), "r"(a[3]), "r"(b[0]), "r"(b[1]));
}
__device__ __forceinline__ void split_f16(float v, unsigned short& h, unsigned short& l) {
    __half hh = __float2half_rn(v);
    __half ll = __float2half_rn(v - __half2float(hh));
    h = __half_as_ushort(hh);
    l = __half_as_ushort(ll);
}
__device__ __forceinline__ unsigned pack_split2(float a, float b, unsigned& lo) {
    unsigned short h0, l0, h1, l1;
    split_f16(a, h0, l0); split_f16(b, h1, l1);
    lo = (unsigned)l0 | ((unsigned)l1 << 16);
    return (unsigned)h0 | ((unsigned)h1 << 16);
}
__device__ __forceinline__ unsigned pack_h2(float a, float b) {
    return (unsigned)__half_as_ushort(__float2half_rn(a)) |
           ((unsigned)__half_as_ushort(__float2half_rn(b)) << 16);
}

// ---------------------------------------------------------------------------
// Prep kernel.  Blocks [0,256): A[w] = deg[w] @ eb[w] via 3-term fp16 mma,
// store fp16 hi/lo + rowsums.  Blocks [256,512): W -> fragment-major g_Wfrag.
// ---------------------------------------------------------------------------
__global__ __launch_bounds__(128) void pab_prep_kernel(const float* __restrict__ deg,
                                                       const float* __restrict__ eb,
                                                       const float* __restrict__ Wp) {
    if (blockIdx.x >= 256) {
        const int idx = (blockIdx.x - 256) * 128 + threadIdx.x;
        const int r = idx & 3, l = (idx >> 2) & 31, blk = idx >> 7;
        const int f4 = blk & 3, ks = (blk >> 2) & 3, nc = (blk >> 4) & 3, kt = blk >> 6;
        const int k = kt * 64 + ks * 16 + (r & 1) * 8 + 2 * (l & 3);
        const int n = nc * 64 + f4 * 16 + ((r >> 1) & 1) * 8 + (l >> 2);
        const unsigned short h0 = __half_as_ushort(__float2half_rn(Wp[n * 256 + k]));
        const unsigned short h1 = __half_as_ushort(__float2half_rn(Wp[n * 256 + k + 1]));
        g_Wfrag[idx] = (unsigned)h0 | ((unsigned)h1 << 16);
        return;
    }
    __shared__ __align__(16) unsigned short dh[64 * 72], dl[64 * 72];
    __shared__ __align__(16) unsigned short eh[64 * 72], el[64 * 72];
    const int w = blockIdx.x, tid = threadIdx.x;
    const int lane = tid & 31, wid = tid >> 5;
    const int lr = lane & 15, lc = lane >> 4;

    for (int j = tid; j < 1024; j += 128) {
        const int row = j >> 4, c4 = (j & 15) * 4;
        float4 v = ((const float4*)(deg + w * 4096))[j];
        unsigned lo0, lo1;
        unsigned hi0 = pack_split2(v.x, v.y, lo0);
        unsigned hi1 = pack_split2(v.z, v.w, lo1);
        *(uint2*)(dh + row * 72 + c4) = make_uint2(hi0, hi1);
        *(uint2*)(dl + row * 72 + c4) = make_uint2(lo0, lo1);
        v = ((const float4*)(eb + w * 4096))[j];
        hi0 = pack_split2(v.x, v.y, lo0);
        hi1 = pack_split2(v.z, v.w, lo1);
        *(uint2*)(eh + row * 72 + c4) = make_uint2(hi0, hi1);
        *(uint2*)(el + row * 72 + c4) = make_uint2(lo0, lo1);
    }
    __syncthreads();

    const unsigned sdh = smem_u32(dh), sdl = smem_u32(dl);
    const unsigned seh = smem_u32(eh), sel = smem_u32(el);
    float acc[8][4];
#pragma unroll
    for (int f = 0; f < 8; ++f)
#pragma unroll
        for (int j = 0; j < 4; ++j) acc[f][j] = 0.f;
#pragma unroll
    for (int ks = 0; ks < 4; ++ks) {
        unsigned Dh[4], Dl[4];
        const unsigned aoff = (unsigned)((wid * 16 + lr) * 144 + (ks * 16 + lc * 8) * 2);
        ldsm4(Dh, sdh + aoff);
        ldsm4(Dl, sdl + aoff);
        const unsigned brow = (unsigned)((ks * 16 + lr) * 144);
#pragma unroll
        for (int f4 = 0; f4 < 4; ++f4) {
            unsigned Eh[4], El[4];
            const unsigned boff = brow + (unsigned)((f4 * 16 + lc * 8) * 2);
            ldsm4t(Eh, seh + boff);
            ldsm4t(El, sel + boff);
            mma16816(acc[2 * f4],     Dh, Eh);
            mma16816(acc[2 * f4],     Dl, Eh);
            mma16816(acc[2 * f4],     Dh, El);
            mma16816(acc[2 * f4 + 1], Dh, Eh + 2);
            mma16816(acc[2 * f4 + 1], Dl, Eh + 2);
            mma16816(acc[2 * f4 + 1], Dh, El + 2);
        }
    }
    float rs0 = 0.f, rs1 = 0.f;
#pragma unroll
    for (int f = 0; f < 8; ++f) {
        rs0 += acc[f][0] + acc[f][1];
        rs1 += acc[f][2] + acc[f][3];
    }
    rs0 += __shfl_xor_sync(0xffffffffu, rs0, 1); rs0 += __shfl_xor_sync(0xffffffffu, rs0, 2);
    rs1 += __shfl_xor_sync(0xffffffffu, rs1, 1); rs1 += __shfl_xor_sync(0xffffffffu, rs1, 2);
    const int r0 = wid * 16 + (lane >> 2);
    if ((lane & 3) == 0) {
        g_rsA[w * 64 + r0] = rs0;
        g_rsA[w * 64 + r0 + 8] = rs1;
    }
#pragma unroll
    for (int f = 0; f < 8; ++f) {
        const int c = f * 8 + (lane & 3) * 2;
        unsigned lo;
        unsigned hi = pack_split2(acc[f][0], acc[f][1], lo);
        *(unsigned*)(g_Ah + w * 4096 + r0 * 64 + c) = hi;
        *(unsigned*)(g_Al + w * 4096 + r0 * 64 + c) = lo;
        hi = pack_split2(acc[f][2], acc[f][3], lo);
        *(unsigned*)(g_Ah + w * 4096 + (r0 + 8) * 64 + c) = hi;
        *(unsigned*)(g_Al + w * 4096 + (r0 + 8) * 64 + c) = lo;
    }
}

// ---------------------------------------------------------------------------
// Main kernel: fused LN (hi-only fp16) + u = (Ah+Al)@xh (2-term, in-place)
//   + out = uh@Wh + rs*bp (32x32 tiles, W fragments via LDG, barrier-free).
// 256 thr, 2 CTAs/SM.  Phase B warp: (wid&3)=16-row block, (wid>>2)=n-half.
// Phase C warp: (wid&1)=32-row block, (wid>>1)=n-quarter; 2 passes.
// ---------------------------------------------------------------------------
__global__ __launch_bounds__(256, 2)
void pab_main_kernel(const float* __restrict__ x,
                     const float* __restrict__ gamma,
                     const float* __restrict__ beta,
                     const float* __restrict__ bp,
                     float* __restrict__ out) {
    extern __shared__ __align__(16) char smb[];
    const unsigned smu = smem_u32(smb);

    const int tid = threadIdx.x;
    const int lane = tid & 31, wid = tid >> 5;
    const int g = wid >> 2;                   // Phase B n-group
    const int mw = wid & 3;                   // Phase B 16-row block
    const int rem = blockIdx.x & 255;         // fi*4 + wi
    const int b = blockIdx.x >> 8;            // 0..7
    const int fi = rem >> 2, wi = rem & 3;
    const int wb = ((b * 256 + fi * 4) * 64 + wi * 16) * ED;

    // ---- setup: bp, rsA, A_w (hi/lo) into smem ----
    ((float*)(smb + OFF_BP))[tid] = bp[tid];
    if (tid < 64) ((float*)(smb + OFF_RS))[tid] = g_rsA[rem * 64 + tid];
#pragma unroll
    for (int u = 0; u < 4; ++u) {
        const int j = tid + u * 256;
        const int hl = j >> 9, jj = j & 511;
        const uint4 v = ((const uint4*)(hl ? g_Al : g_Ah))[rem * 512 + jj];
        *(uint4*)(smb + OFF_A + hl * 9216 + (jj >> 3) * 144 + (jj & 7) * 16) = v;
    }

    // ---- LayerNorm -> xn hi (padded row-major fp16), 8 rows per warp ----
    {
        float gr[8], br[8];
#pragma unroll
        for (int u = 0; u < 8; ++u) { gr[u] = gamma[lane * 8 + u]; br[u] = beta[lane * 8 + u]; }
#pragma unroll
        for (int r = 0; r < 8; ++r) {
            const int l = wid * 8 + r;
            const float* xr = x + wb + ((l >> 4) * 64 + (l & 15)) * ED;
            float4 a4 = *(const float4*)(xr + lane * 8);
            float4 b4 = *(const float4*)(xr + lane * 8 + 4);
            float v[8] = {a4.x, a4.y, a4.z, a4.w, b4.x, b4.y, b4.z, b4.w};
            float s = 0.f, s2 = 0.f;
#pragma unroll
            for (int u = 0; u < 8; ++u) { s += v[u]; s2 = fmaf(v[u], v[u], s2); }
#pragma unroll
            for (int o = 16; o > 0; o >>= 1) {
                s += __shfl_xor_sync(0xffffffffu, s, o);
                s2 += __shfl_xor_sync(0xffffffffu, s2, o);
            }
            const float mu = s * (1.f / 256.f);
            const float var = fmaf(-mu, mu, s2 * (1.f / 256.f));
            const float rstd = rsqrtf(var + 1e-5f);
            uint4 ph;
            ph.x = pack_h2((v[0] - mu) * rstd * gr[0] + br[0],
                           (v[1] - mu) * rstd * gr[1] + br[1]);
            ph.y = pack_h2((v[2] - mu) * rstd * gr[2] + br[2],
                           (v[3] - mu) * rstd * gr[3] + br[3]);
            ph.z = pack_h2((v[4] - mu) * rstd * gr[4] + br[4],
                           (v[5] - mu) * rstd * gr[5] + br[5]);
            ph.w = pack_h2((v[6] - mu) * rstd * gr[6] + br[6],
                           (v[7] - mu) * rstd * gr[7] + br[7]);
            *(uint4*)(smb + OFF_XH + l * XROW + lane * 16) = ph;
        }
    }
    __syncthreads();

    // ---- Phase B: u[p][e] = sum_q (Ah+Al)[p][q]*xh[q][e], in-place (hi out).
    //      Group g handles n-chunks {2g, 2g+1}; rows = mw*16..+15. ----
    const int lr = lane & 15, lc = lane >> 4;
    for (int jj = 0; jj < 2; ++jj) {
        const int nc = g * 2 + jj;
        float acc[8][4];
#pragma unroll
        for (int f = 0; f < 8; ++f)
#pragma unroll
            for (int j = 0; j < 4; ++j) acc[f][j] = 0.f;

#pragma unroll
        for (int ks = 0; ks < 4; ++ks) {
            unsigned Ah[4], Al[4];
            const unsigned aoff = (unsigned)((mw * 16 + lr) * 144 + (ks * 16 + lc * 8) * 2);
            ldsm4(Ah, smu + OFF_A + aoff);
            ldsm4(Al, smu + OFF_A + 9216u + aoff);
            const unsigned brow = (unsigned)((ks * 16 + lr) * XROW);
#pragma unroll
            for (int f4 = 0; f4 < 4; ++f4) {
                const unsigned bcol = (unsigned)((nc * 64 + f4 * 16 + lc * 8) * 2);
                unsigned Bh[4];
                ldsm4t(Bh, smu + OFF_XH + brow + bcol);
                mma16816(acc[2 * f4],     Ah, Bh);
                mma16816(acc[2 * f4],     Al, Bh);
                mma16816(acc[2 * f4 + 1], Ah, Bh + 2);
                mma16816(acc[2 * f4 + 1], Al, Bh + 2);
            }
        }
        __syncthreads();   // all reads of this chunk's columns done -> overwrite
        const int r0 = mw * 16 + (lane >> 2);
#pragma unroll
        for (int f = 0; f < 8; ++f) {
            const int c = nc * 64 + f * 8 + (lane & 3) * 2;
            *(unsigned*)(smb + OFF_XH + r0 * XROW + c * 2) = pack_h2(acc[f][0], acc[f][1]);
            *(unsigned*)(smb + OFF_XH + (r0 + 8) * XROW + c * 2) = pack_h2(acc[f][2], acc[f][3]);
        }
    }
    __syncthreads();       // U fully written before Phase C reads (rows re-owned)

    // ---- Phase C: out[m][n] = sum_k uh[m][k] * Wh[k][n] + rs[m]*bp[n].
    //      32x32 warp tiles: rows (wid&1)*32, n-quarter q=wid>>1; 2 passes.
    //      W b-fragments via LDG (double-buffered); NO barriers. ----
    const float* bps = (const float*)(smb + OFF_BP);
    const float* rss = (const float*)(smb + OFF_RS);
    const int r0c = (wid & 1) * 32;
    const int q = wid >> 1;
    for (int j = 0; j < 2; ++j) {
        const int nc32 = q + j * 4;
        const int nc64 = nc32 >> 1;
        const int f4b = (nc32 & 1) * 2;
        float acc[8][4];               // f = mb*4 + t*2 + n8
#pragma unroll
        for (int f = 0; f < 8; ++f)
#pragma unroll
            for (int jr = 0; jr < 4; ++jr) acc[f][jr] = 0.f;

        unsigned Wf[2][8];
        {   // prefetch step 0: (kt=0, ks=0), two f4 blocks
            const unsigned* p = g_Wfrag + (nc64 * 16 + f4b) * 128 + lane * 4;
            *(uint4*)&Wf[0][0] = *(const uint4*)(p);
            *(uint4*)&Wf[0][4] = *(const uint4*)(p + 128);
        }
#pragma unroll
        for (int kt = 0; kt < 4; ++kt) {
#pragma unroll
            for (int ks = 0; ks < 4; ++ks) {
                const int step = kt * 4 + ks;
                const int pb = step & 1;
                if (step < 15) {   // prefetch next (kt,ks)
                    const int ns = step + 1;
                    const int nkt = ns >> 2, nks = ns & 3;
                    const unsigned* p =
                        g_Wfrag + (((nkt * 4 + nc64) * 16 + nks * 4 + f4b) * 128) + lane * 4;
                    *(uint4*)&Wf[pb ^ 1][0] = *(const uint4*)(p);
                    *(uint4*)&Wf[pb ^ 1][4] = *(const uint4*)(p + 128);
                }
                unsigned Uh[8];
                const unsigned kby = (unsigned)((kt * 64 + ks * 16 + lc * 8) * 2);
                ldsm4(Uh,     smu + OFF_XH + (unsigned)((r0c + lr) * XROW) + kby);
                ldsm4(Uh + 4, smu + OFF_XH + (unsigned)((r0c + 16 + lr) * XROW) + kby);
                const unsigned* Wc = Wf[pb];
#pragma unroll
                for (int t = 0; t < 2; ++t) {
                    mma16816(acc[t * 2],         Uh,     Wc + t * 4);
                    mma16816(acc[t * 2 + 1],     Uh,     Wc + t * 4 + 2);
                    mma16816(acc[4 + t * 2],     Uh + 4, Wc + t * 4);
                    mma16816(acc[4 + t * 2 + 1], Uh + 4, Wc + t * 4 + 2);
                }
            }
        }
        // epilogue for this 32-col chunk: direct global store
#pragma unroll
        for (int mb = 0; mb < 2; ++mb) {
            const int m0 = r0c + mb * 16 + (lane >> 2);
#pragma unroll
            for (int t = 0; t < 2; ++t) {
#pragma unroll
                for (int n8 = 0; n8 < 2; ++n8) {
                    const int f = mb * 4 + t * 2 + n8;
                    const int c = nc32 * 32 + t * 16 + n8 * 8 + (lane & 3) * 2;
                    const float b0 = bps[c], b1 = bps[c + 1];
#pragma unroll
                    for (int half = 0; half < 2; ++half) {
                        const int l = m0 + half * 8;
                        const float rs = rss[l];
                        float2 v;
                        v.x = acc[f][half * 2 + 0] + rs * b0;
                        v.y = acc[f][half * 2 + 1] + rs * b1;
                        *(float2*)(out + wb + ((l >> 4) * 64 + (l & 15)) * ED + c) = v;
                    }
                }
            }
        }
    }
}

// ---------------------------------------------------------------------------
extern "C" void kernel_launch(void* const* d_in, const int* in_sizes, int n_in,
                              void* d_out, int out_size) {
    const float* x     = (const float*)d_in[0];
    const float* gamma = (const float*)d_in[1];
    const float* beta  = (const float*)d_in[2];
    const float* Wp    = (const float*)d_in[3];
    const float* bp    = (const float*)d_in[4];
    const float* eb    = (const float*)d_in[5];
    const float* deg   = (const float*)d_in[6];
    float* out = (float*)d_out;

    cudaFuncSetAttribute(pab_main_kernel,
                         cudaFuncAttributeMaxDynamicSharedMemorySize, (int)SMEM_BYTES);

    pab_prep_kernel<<<512, 128>>>(deg, eb, Wp);
    pab_main_kernel<<<2048, 256, SMEM_BYTES>>>(x, gamma, beta, bp, out);
}